// round 1
// baseline (speedup 1.0000x reference)
#include <cuda_runtime.h>

#define HEADS 16
#define DIMD 128
#define NSEQ 2048
#define NEGV (-1e9f)
#define INV_SQRT_N 0.02209708691207961f  /* 1/sqrt(2048) */

// ---------------- scratch (static device globals; no allocations) ----------------
__device__ __align__(16) float g_qp[HEADS * NSEQ * DIMD];
__device__ __align__(16) float g_kp[HEADS * NSEQ * DIMD];
__device__ __align__(16) float g_vp[HEADS * NSEQ * DIMD];
__device__ __align__(16) float g_ctx[NSEQ * HEADS * DIMD];

// =====================================================================
// Kernel 1: per-head input projections  qp/kp/vp[h,n,e] = x[n,:] @ W[h,:,:]
// grid (16, 16, 3) : (row-tile, head, which-of-qkv). 256 threads.
// Tile: 128 rows x 128 cols, K=128 fully in smem.
// =====================================================================
__global__ void __launch_bounds__(256) proj_kernel(
    const float* __restrict__ q, const float* __restrict__ k,
    const float* __restrict__ v, const float* __restrict__ Qw,
    const float* __restrict__ Kw, const float* __restrict__ Vw) {
  extern __shared__ float sm[];
  float(*At)[132] = reinterpret_cast<float(*)[132]>(sm);              // [d][r] (transposed)
  float(*Ws)[132] = reinterpret_cast<float(*)[132]>(sm + 128 * 132);  // [d][e]

  const int which = blockIdx.z;
  const float* A = (which == 0) ? q : (which == 1) ? k : v;
  const float* W = (which == 0) ? Qw : (which == 1) ? Kw : Vw;
  float* C = (which == 0) ? g_qp : (which == 1) ? g_kp : g_vp;
  const int h = blockIdx.y;
  const int n0 = blockIdx.x * 128;
  const int tid = threadIdx.x;

  // load 128 activation rows, store transposed
  for (int idx = tid; idx < 128 * 32; idx += 256) {
    int r = idx >> 5, d4 = (idx & 31) * 4;
    float4 t = *reinterpret_cast<const float4*>(A + (n0 + r) * DIMD + d4);
    At[d4 + 0][r] = t.x; At[d4 + 1][r] = t.y;
    At[d4 + 2][r] = t.z; At[d4 + 3][r] = t.w;
  }
  const float* Wh = W + h * DIMD * DIMD;
  for (int idx = tid; idx < 128 * 32; idx += 256) {
    int d = idx >> 5, e4 = (idx & 31) * 4;
    *reinterpret_cast<float4*>(&Ws[d][e4]) =
        *reinterpret_cast<const float4*>(Wh + d * DIMD + e4);
  }
  __syncthreads();

  const int ty = tid >> 4, tx = tid & 15;
  const int r0 = ty * 8;
  const int c0 = tx * 4;  // cols c0..c0+3 and 64+c0..64+c0+3

  float acc[8][8];
#pragma unroll
  for (int i = 0; i < 8; i++)
#pragma unroll
    for (int j = 0; j < 8; j++) acc[i][j] = 0.f;

#pragma unroll 4
  for (int d = 0; d < DIMD; d++) {
    float4 a0 = *reinterpret_cast<const float4*>(&At[d][r0]);
    float4 a1 = *reinterpret_cast<const float4*>(&At[d][r0 + 4]);
    float4 b0 = *reinterpret_cast<const float4*>(&Ws[d][c0]);
    float4 b1 = *reinterpret_cast<const float4*>(&Ws[d][64 + c0]);
    float a[8] = {a0.x, a0.y, a0.z, a0.w, a1.x, a1.y, a1.z, a1.w};
    float b[8] = {b0.x, b0.y, b0.z, b0.w, b1.x, b1.y, b1.z, b1.w};
#pragma unroll
    for (int i = 0; i < 8; i++)
#pragma unroll
      for (int j = 0; j < 8; j++) acc[i][j] = fmaf(a[i], b[j], acc[i][j]);
  }

  float* Cb = C + (h * NSEQ + n0) * DIMD;
#pragma unroll
  for (int i = 0; i < 8; i++) {
    float4 w0 = make_float4(acc[i][0], acc[i][1], acc[i][2], acc[i][3]);
    float4 w1 = make_float4(acc[i][4], acc[i][5], acc[i][6], acc[i][7]);
    *reinterpret_cast<float4*>(Cb + (r0 + i) * DIMD + c0) = w0;
    *reinterpret_cast<float4*>(Cb + (r0 + i) * DIMD + 64 + c0) = w1;
  }
}

// =====================================================================
// Kernel 2: masked attention, flash-style. "rows" = kp index i,
// "cols" = qp index j.  att[i,j] = kp[i]·qp[j]; softmax over j; O = P @ vp.
// grid (32, 16) : (row-tile of 64, head). 256 threads.
// =====================================================================
__global__ void __launch_bounds__(256) attn_kernel(const int* __restrict__ mask) {
  extern __shared__ float sm[];
  float(*Kst)[68] = reinterpret_cast<float(*)[68]>(sm);                 // [d][r] 128x68
  float(*Qst)[68] = reinterpret_cast<float(*)[68]>(sm + 128 * 68);      // [d][c] 128x68
  float(*Vs)[132] = reinterpret_cast<float(*)[132]>(sm + 2 * 128 * 68); // [j][d] 64x132
  float(*Pt)[68] = reinterpret_cast<float(*)[68]>(sm + 2 * 128 * 68 + 64 * 132); // [c][r]
  float* row_m = sm + 2 * 128 * 68 + 64 * 132 + 64 * 68;
  float* row_l = row_m + 64;
  float* row_s = row_l + 64;

  const int h = blockIdx.y;
  const int i0 = blockIdx.x * 64;
  const int tid = threadIdx.x;
  const int ty = tid >> 4, tx = tid & 15;
  const int r0 = ty * 4;
  const int c0 = tx * 4;

  const float* kp = g_kp + h * NSEQ * DIMD;
  const float* qp = g_qp + h * NSEQ * DIMD;
  const float* vp = g_vp + h * NSEQ * DIMD;

  // K tile (persistent), transposed
  for (int idx = tid; idx < 64 * 32; idx += 256) {
    int r = idx >> 5, d4 = (idx & 31) * 4;
    float4 t = *reinterpret_cast<const float4*>(kp + (i0 + r) * DIMD + d4);
    Kst[d4 + 0][r] = t.x; Kst[d4 + 1][r] = t.y;
    Kst[d4 + 2][r] = t.z; Kst[d4 + 3][r] = t.w;
  }
  if (tid < 64) { row_m[tid] = -3.0e38f; row_l[tid] = 0.f; }

  float o[4][8];
#pragma unroll
  for (int i = 0; i < 4; i++)
#pragma unroll
    for (int j = 0; j < 8; j++) o[i][j] = 0.f;

  for (int jt = 0; jt < NSEQ / 64; jt++) {
    const int j0 = jt * 64;
    __syncthreads();  // protects Qst/Vs/Pt reuse (and first-iter fills)

    for (int idx = tid; idx < 64 * 32; idx += 256) {
      int c = idx >> 5, d4 = (idx & 31) * 4;
      float4 t = *reinterpret_cast<const float4*>(qp + (j0 + c) * DIMD + d4);
      Qst[d4 + 0][c] = t.x; Qst[d4 + 1][c] = t.y;
      Qst[d4 + 2][c] = t.z; Qst[d4 + 3][c] = t.w;
    }
    for (int idx = tid; idx < 64 * 32; idx += 256) {
      int r = idx >> 5, d4 = (idx & 31) * 4;
      *reinterpret_cast<float4*>(&Vs[r][d4]) =
          *reinterpret_cast<const float4*>(vp + (j0 + r) * DIMD + d4);
    }
    __syncthreads();

    // S = K Q^T  (4x4 per thread)
    float s[4][4];
#pragma unroll
    for (int i = 0; i < 4; i++)
#pragma unroll
      for (int j = 0; j < 4; j++) s[i][j] = 0.f;

#pragma unroll 4
    for (int d = 0; d < DIMD; d++) {
      float4 a = *reinterpret_cast<const float4*>(&Kst[d][r0]);
      float4 b = *reinterpret_cast<const float4*>(&Qst[d][c0]);
      s[0][0] = fmaf(a.x, b.x, s[0][0]); s[0][1] = fmaf(a.x, b.y, s[0][1]);
      s[0][2] = fmaf(a.x, b.z, s[0][2]); s[0][3] = fmaf(a.x, b.w, s[0][3]);
      s[1][0] = fmaf(a.y, b.x, s[1][0]); s[1][1] = fmaf(a.y, b.y, s[1][1]);
      s[1][2] = fmaf(a.y, b.z, s[1][2]); s[1][3] = fmaf(a.y, b.w, s[1][3]);
      s[2][0] = fmaf(a.z, b.x, s[2][0]); s[2][1] = fmaf(a.z, b.y, s[2][1]);
      s[2][2] = fmaf(a.z, b.z, s[2][2]); s[2][3] = fmaf(a.z, b.w, s[2][3]);
      s[3][0] = fmaf(a.w, b.x, s[3][0]); s[3][1] = fmaf(a.w, b.y, s[3][1]);
      s[3][2] = fmaf(a.w, b.z, s[3][2]); s[3][3] = fmaf(a.w, b.w, s[3][3]);
    }

    // mask + scale, store column-major into Pt
#pragma unroll
    for (int j = 0; j < 4; j++) {
      const int gj = j0 + c0 + j;
#pragma unroll
      for (int i = 0; i < 4; i++) {
        int mv = mask[(i0 + r0 + i) * NSEQ + gj];
        Pt[c0 + j][r0 + i] = mv ? s[i][j] * INV_SQRT_N : NEGV;
      }
    }
    __syncthreads();

    // online softmax per row (64 threads, conflict-free column scans)
    if (tid < 64) {
      const int r = tid;
      float m_old = row_m[r];
      float mx = m_old;
      for (int c = 0; c < 64; c++) mx = fmaxf(mx, Pt[c][r]);
      float scale = __expf(m_old - mx);
      float sum = 0.f;
      for (int c = 0; c < 64; c++) {
        float p = __expf(Pt[c][r] - mx);
        Pt[c][r] = p;
        sum += p;
      }
      row_l[r] = row_l[r] * scale + sum;
      row_m[r] = mx;
      row_s[r] = scale;
    }
    __syncthreads();

    // rescale O, then O += P @ V
    {
      float sc[4] = {row_s[r0], row_s[r0 + 1], row_s[r0 + 2], row_s[r0 + 3]};
#pragma unroll
      for (int i = 0; i < 4; i++)
#pragma unroll
        for (int j = 0; j < 8; j++) o[i][j] *= sc[i];
    }

#pragma unroll 4
    for (int j = 0; j < 64; j++) {
      float4 p = *reinterpret_cast<const float4*>(&Pt[j][r0]);
      float4 va = *reinterpret_cast<const float4*>(&Vs[j][c0]);
      float4 vb = *reinterpret_cast<const float4*>(&Vs[j][64 + c0]);
      o[0][0] = fmaf(p.x, va.x, o[0][0]); o[0][1] = fmaf(p.x, va.y, o[0][1]);
      o[0][2] = fmaf(p.x, va.z, o[0][2]); o[0][3] = fmaf(p.x, va.w, o[0][3]);
      o[0][4] = fmaf(p.x, vb.x, o[0][4]); o[0][5] = fmaf(p.x, vb.y, o[0][5]);
      o[0][6] = fmaf(p.x, vb.z, o[0][6]); o[0][7] = fmaf(p.x, vb.w, o[0][7]);
      o[1][0] = fmaf(p.y, va.x, o[1][0]); o[1][1] = fmaf(p.y, va.y, o[1][1]);
      o[1][2] = fmaf(p.y, va.z, o[1][2]); o[1][3] = fmaf(p.y, va.w, o[1][3]);
      o[1][4] = fmaf(p.y, vb.x, o[1][4]); o[1][5] = fmaf(p.y, vb.y, o[1][5]);
      o[1][6] = fmaf(p.y, vb.z, o[1][6]); o[1][7] = fmaf(p.y, vb.w, o[1][7]);
      o[2][0] = fmaf(p.z, va.x, o[2][0]); o[2][1] = fmaf(p.z, va.y, o[2][1]);
      o[2][2] = fmaf(p.z, va.z, o[2][2]); o[2][3] = fmaf(p.z, va.w, o[2][3]);
      o[2][4] = fmaf(p.z, vb.x, o[2][4]); o[2][5] = fmaf(p.z, vb.y, o[2][5]);
      o[2][6] = fmaf(p.z, vb.z, o[2][6]); o[2][7] = fmaf(p.z, vb.w, o[2][7]);
      o[3][0] = fmaf(p.w, va.x, o[3][0]); o[3][1] = fmaf(p.w, va.y, o[3][1]);
      o[3][2] = fmaf(p.w, va.z, o[3][2]); o[3][3] = fmaf(p.w, va.w, o[3][3]);
      o[3][4] = fmaf(p.w, vb.x, o[3][4]); o[3][5] = fmaf(p.w, vb.y, o[3][5]);
      o[3][6] = fmaf(p.w, vb.z, o[3][6]); o[3][7] = fmaf(p.w, vb.w, o[3][7]);
    }
  }

  // epilogue: normalize and write to concat buffer ctx[n][h*128+d]
#pragma unroll
  for (int i = 0; i < 4; i++) {
    float linv = 1.f / row_l[r0 + i];
    float4 w0 = make_float4(o[i][0] * linv, o[i][1] * linv, o[i][2] * linv, o[i][3] * linv);
    float4 w1 = make_float4(o[i][4] * linv, o[i][5] * linv, o[i][6] * linv, o[i][7] * linv);
    float* dst = g_ctx + (i0 + r0 + i) * (HEADS * DIMD) + h * DIMD;
    *reinterpret_cast<float4*>(dst + c0) = w0;
    *reinterpret_cast<float4*>(dst + 64 + c0) = w1;
  }
}

// =====================================================================
// Kernel 3: out = ctx[2048,2048] @ last[2048,128].  grid 64 blocks x 256 thr.
// =====================================================================
__global__ void __launch_bounds__(256) out_kernel(const float* __restrict__ last,
                                                  float* __restrict__ out) {
  __shared__ float As[32][68];
  __shared__ float Bs[64][132];
  const int n0 = blockIdx.x * 32;
  const int tid = threadIdx.x;
  const int ty = tid >> 5, tx = tid & 31;
  const int r0 = ty * 4, c0 = tx * 4;

  float acc[4][4];
#pragma unroll
  for (int i = 0; i < 4; i++)
#pragma unroll
    for (int j = 0; j < 4; j++) acc[i][j] = 0.f;

  for (int k0 = 0; k0 < HEADS * DIMD; k0 += 64) {
    __syncthreads();
    for (int idx = tid; idx < 32 * 16; idx += 256) {
      int r = idx >> 4, c4 = (idx & 15) * 4;
      *reinterpret_cast<float4*>(&As[r][c4]) = *reinterpret_cast<const float4*>(
          g_ctx + (n0 + r) * (HEADS * DIMD) + k0 + c4);
    }
    for (int idx = tid; idx < 64 * 32; idx += 256) {
      int kk = idx >> 5, e4 = (idx & 31) * 4;
      *reinterpret_cast<float4*>(&Bs[kk][e4]) =
          *reinterpret_cast<const float4*>(last + (k0 + kk) * DIMD + e4);
    }
    __syncthreads();
#pragma unroll 4
    for (int kk = 0; kk < 64; kk++) {
      float4 b = *reinterpret_cast<const float4*>(&Bs[kk][c0]);
      float a0 = As[r0][kk], a1 = As[r0 + 1][kk], a2 = As[r0 + 2][kk], a3 = As[r0 + 3][kk];
      acc[0][0] = fmaf(a0, b.x, acc[0][0]); acc[0][1] = fmaf(a0, b.y, acc[0][1]);
      acc[0][2] = fmaf(a0, b.z, acc[0][2]); acc[0][3] = fmaf(a0, b.w, acc[0][3]);
      acc[1][0] = fmaf(a1, b.x, acc[1][0]); acc[1][1] = fmaf(a1, b.y, acc[1][1]);
      acc[1][2] = fmaf(a1, b.z, acc[1][2]); acc[1][3] = fmaf(a1, b.w, acc[1][3]);
      acc[2][0] = fmaf(a2, b.x, acc[2][0]); acc[2][1] = fmaf(a2, b.y, acc[2][1]);
      acc[2][2] = fmaf(a2, b.z, acc[2][2]); acc[2][3] = fmaf(a2, b.w, acc[2][3]);
      acc[3][0] = fmaf(a3, b.x, acc[3][0]); acc[3][1] = fmaf(a3, b.y, acc[3][1]);
      acc[3][2] = fmaf(a3, b.z, acc[3][2]); acc[3][3] = fmaf(a3, b.w, acc[3][3]);
    }
  }
#pragma unroll
  for (int i = 0; i < 4; i++) {
    float4 w = make_float4(acc[i][0], acc[i][1], acc[i][2], acc[i][3]);
    *reinterpret_cast<float4*>(out + (n0 + r0 + i) * DIMD + c0) = w;
  }
}

// =====================================================================
extern "C" void kernel_launch(void* const* d_in, const int* in_sizes, int n_in,
                              void* d_out, int out_size) {
  // locate mask robustly by its unique element count (N*N)
  int mi = -1;
  for (int i = 0; i < n_in; i++)
    if (in_sizes[i] == NSEQ * NSEQ) { mi = i; break; }
  if (mi < 0) mi = 3;

  const void* p[7];
  int np = 0;
  for (int i = 0; i < n_in && np < 7; i++) {
    if (i == mi) continue;
    p[np++] = d_in[i];
  }
  const float* q = (const float*)p[0];
  const float* k = (const float*)p[1];
  const float* v = (const float*)p[2];
  const float* Qw = (const float*)p[3];
  const float* Kw = (const float*)p[4];
  const float* Vw = (const float*)p[5];
  const float* last = (const float*)p[6];
  const int* mask = (const int*)d_in[mi];
  float* out = (float*)d_out;

  const int PROJ_SMEM = 2 * 128 * 132 * 4;                                   // 135168
  const int ATTN_SMEM = (2 * 128 * 68 + 64 * 132 + 64 * 68 + 3 * 64) * 4;    // 121600

  cudaFuncSetAttribute(proj_kernel, cudaFuncAttributeMaxDynamicSharedMemorySize, PROJ_SMEM);
  cudaFuncSetAttribute(attn_kernel, cudaFuncAttributeMaxDynamicSharedMemorySize, ATTN_SMEM);

  proj_kernel<<<dim3(NSEQ / 128, HEADS, 3), 256, PROJ_SMEM>>>(q, k, v, Qw, Kw, Vw);
  attn_kernel<<<dim3(NSEQ / 64, HEADS), 256, ATTN_SMEM>>>(mask);
  out_kernel<<<NSEQ / 32, 256>>>(last, out);
}

// round 3
// speedup vs baseline: 3.1542x; 3.1542x over previous
#include <cuda_runtime.h>
#include <cstdint>

#define HEADS 16
#define DIMD 128
#define NSEQ 2048
#define INV_SQRT_N 0.02209708691207961f /* 1/sqrt(2048) */

// ---------------- scratch (static device globals; no allocations) ----------------
__device__ __align__(16) float g_qp[HEADS * NSEQ * DIMD];
__device__ __align__(16) float g_kp[HEADS * NSEQ * DIMD];
__device__ __align__(16) float g_vp[HEADS * NSEQ * DIMD];
__device__ __align__(16) float g_ctx[NSEQ * HEADS * DIMD];
__device__ __align__(16) unsigned g_mbits[NSEQ * (NSEQ / 32)];

// ---------------- helpers ----------------
__device__ __forceinline__ uint32_t f2tf(float x) {
  uint32_t r;
  asm("cvt.rna.tf32.f32 %0, %1;" : "=r"(r) : "f"(x));
  return r;
}

__device__ __forceinline__ void mma_tf32(float c[4], const uint32_t a[4],
                                         uint32_t b0, uint32_t b1) {
  asm volatile(
      "mma.sync.aligned.m16n8k8.row.col.f32.tf32.tf32.f32 "
      "{%0,%1,%2,%3}, {%4,%5,%6,%7}, {%8,%9}, {%0,%1,%2,%3};"
      : "+f"(c[0]), "+f"(c[1]), "+f"(c[2]), "+f"(c[3])
      : "r"(a[0]), "r"(a[1]), "r"(a[2]), "r"(a[3]), "r"(b0), "r"(b1));
}

// ======================= kernel 0: pack mask into bits =======================
__global__ void __launch_bounds__(256) maskbits_kernel(const int* __restrict__ mask) {
  int w = blockIdx.x * 8 + (threadIdx.x >> 5);
  int lane = threadIdx.x & 31;
  int m = mask[(size_t)w * 32 + lane];
  unsigned bits = __ballot_sync(0xffffffffu, m != 0);
  if (lane == 0) g_mbits[w] = bits;
}

// ======================= kernel 1: projections (fp32 FFMA) ==================
__global__ void __launch_bounds__(256) proj_kernel(
    const float* __restrict__ q, const float* __restrict__ k,
    const float* __restrict__ v, const float* __restrict__ Qw,
    const float* __restrict__ Kw, const float* __restrict__ Vw) {
  extern __shared__ float sm[];
  float(*At)[132] = reinterpret_cast<float(*)[132]>(sm);
  float(*Ws)[132] = reinterpret_cast<float(*)[132]>(sm + 128 * 132);

  const int which = blockIdx.z;
  const float* A = (which == 0) ? q : (which == 1) ? k : v;
  const float* W = (which == 0) ? Qw : (which == 1) ? Kw : Vw;
  float* C = (which == 0) ? g_qp : (which == 1) ? g_kp : g_vp;
  const int h = blockIdx.y;
  const int n0 = blockIdx.x * 128;
  const int tid = threadIdx.x;

  for (int idx = tid; idx < 128 * 32; idx += 256) {
    int r = idx >> 5, d4 = (idx & 31) * 4;
    float4 t = *reinterpret_cast<const float4*>(A + (n0 + r) * DIMD + d4);
    At[d4 + 0][r] = t.x; At[d4 + 1][r] = t.y;
    At[d4 + 2][r] = t.z; At[d4 + 3][r] = t.w;
  }
  const float* Wh = W + h * DIMD * DIMD;
  for (int idx = tid; idx < 128 * 32; idx += 256) {
    int d = idx >> 5, e4 = (idx & 31) * 4;
    *reinterpret_cast<float4*>(&Ws[d][e4]) =
        *reinterpret_cast<const float4*>(Wh + d * DIMD + e4);
  }
  __syncthreads();

  const int ty = tid >> 4, tx = tid & 15;
  const int r0 = ty * 8, c0 = tx * 4;

  float acc[8][8];
#pragma unroll
  for (int i = 0; i < 8; i++)
#pragma unroll
    for (int j = 0; j < 8; j++) acc[i][j] = 0.f;

#pragma unroll 4
  for (int d = 0; d < DIMD; d++) {
    float4 a0 = *reinterpret_cast<const float4*>(&At[d][r0]);
    float4 a1 = *reinterpret_cast<const float4*>(&At[d][r0 + 4]);
    float4 b0 = *reinterpret_cast<const float4*>(&Ws[d][c0]);
    float4 b1 = *reinterpret_cast<const float4*>(&Ws[d][64 + c0]);
    float a[8] = {a0.x, a0.y, a0.z, a0.w, a1.x, a1.y, a1.z, a1.w};
    float b[8] = {b0.x, b0.y, b0.z, b0.w, b1.x, b1.y, b1.z, b1.w};
#pragma unroll
    for (int i = 0; i < 8; i++)
#pragma unroll
      for (int j = 0; j < 8; j++) acc[i][j] = fmaf(a[i], b[j], acc[i][j]);
  }

  float* Cb = C + (h * NSEQ + n0) * DIMD;
#pragma unroll
  for (int i = 0; i < 8; i++) {
    float4 w0 = make_float4(acc[i][0], acc[i][1], acc[i][2], acc[i][3]);
    float4 w1 = make_float4(acc[i][4], acc[i][5], acc[i][6], acc[i][7]);
    *reinterpret_cast<float4*>(Cb + (r0 + i) * DIMD + c0) = w0;
    *reinterpret_cast<float4*>(Cb + (r0 + i) * DIMD + 64 + c0) = w1;
  }
}

// ======================= kernel 2: mma.sync tf32 attention ===================
// Block: one head h, 128 K-rows (i). 8 warps; warp tile = 32 (m) x 64 (n).
// Loop over 16 j-tiles of 128 q-cols:
//   S = Kp·Qp^T  (tf32 mma, fp32 acc, regs)
//   p = mask ? exp(s/sqrt(N)) : 0   (no row max: logits bounded)
//   P -> smem (tf32), O += P·Vp (tf32 mma, fp32 acc in regs, no rescale)
// Epilogue: O /= rowsum, write to ctx.
#define KST 132
#define QST 132
#define VST 136
#define SM_K 0
#define SM_Q (128 * KST)
#define SM_V (2 * 128 * 132)
#define SM_L (2 * 128 * 132 + 128 * VST)
#define ATTN_SMEM_FLOATS (2 * 128 * 132 + 128 * VST + 256)

__global__ void __launch_bounds__(256) attn_mma_kernel() {
  extern __shared__ float sm[];
  uint32_t* Ksu = reinterpret_cast<uint32_t*>(sm + SM_K);
  uint32_t* Qsu = reinterpret_cast<uint32_t*>(sm + SM_Q);  // also holds P
  uint32_t* Vsu = reinterpret_cast<uint32_t*>(sm + SM_V);
  float* l_sh = sm + SM_L;  // [2][128]

  const int tid = threadIdx.x;
  const int wid = tid >> 5;
  const int lane = tid & 31;
  const int qr = lane >> 2;   // 0..7
  const int qc = lane & 3;    // 0..3
  const int wm = (wid & 3) * 32;   // warp m-block (rows of K)
  const int wn = (wid >> 2) * 64;  // warp n-half (cols: j for S, d for O)

  const int h = blockIdx.y;
  const int i0 = blockIdx.x * 128;

  const float* kp = g_kp + (size_t)h * NSEQ * DIMD;
  const float* qp = g_qp + (size_t)h * NSEQ * DIMD;
  const float* vp = g_vp + (size_t)h * NSEQ * DIMD;

  // ---- K tile (persistent), tf32-converted, row-major [i][d], stride 132
  for (int idx = tid; idx < 128 * 32; idx += 256) {
    int r = idx >> 5, c4 = (idx & 31) << 2;
    float4 t = *reinterpret_cast<const float4*>(kp + (size_t)(i0 + r) * DIMD + c4);
    uint4 u = make_uint4(f2tf(t.x), f2tf(t.y), f2tf(t.z), f2tf(t.w));
    *reinterpret_cast<uint4*>(Ksu + r * KST + c4) = u;
  }

  float O[2][8][4];
#pragma unroll
  for (int mt = 0; mt < 2; mt++)
#pragma unroll
    for (int nt = 0; nt < 8; nt++)
#pragma unroll
      for (int e = 0; e < 4; e++) O[mt][nt][e] = 0.f;
  float L[4] = {0.f, 0.f, 0.f, 0.f};

  const int row_rel[4] = {qr, qr + 8, qr + 16, qr + 24};

  for (int jt = 0; jt < NSEQ / 128; jt++) {
    const int j0 = jt * 128;
    __syncthreads();  // previous PV done reading Ps(=Qs buffer) and Vs

    // Q tile natural [j][d]; V tile natural [j][d] stride 136
    for (int idx = tid; idx < 128 * 32; idx += 256) {
      int r = idx >> 5, c4 = (idx & 31) << 2;
      float4 t = *reinterpret_cast<const float4*>(qp + (size_t)(j0 + r) * DIMD + c4);
      uint4 u = make_uint4(f2tf(t.x), f2tf(t.y), f2tf(t.z), f2tf(t.w));
      *reinterpret_cast<uint4*>(Qsu + r * QST + c4) = u;
      float4 tv = *reinterpret_cast<const float4*>(vp + (size_t)(j0 + r) * DIMD + c4);
      uint4 uv = make_uint4(f2tf(tv.x), f2tf(tv.y), f2tf(tv.z), f2tf(tv.w));
      *reinterpret_cast<uint4*>(Vsu + r * VST + c4) = uv;
    }
    __syncthreads();

    // ---- S = K · Q^T  (m=i 32, n=j 64, k=d 128)
    float S[2][8][4];
#pragma unroll
    for (int mt = 0; mt < 2; mt++)
#pragma unroll
      for (int nt = 0; nt < 8; nt++)
#pragma unroll
        for (int e = 0; e < 4; e++) S[mt][nt][e] = 0.f;

#pragma unroll 4
    for (int k0 = 0; k0 < 128; k0 += 8) {
      uint32_t A[2][4];
#pragma unroll
      for (int mt = 0; mt < 2; mt++) {
        const uint32_t* ab = Ksu + (wm + mt * 16 + qr) * KST + k0 + qc;
        A[mt][0] = ab[0];
        A[mt][1] = ab[8 * KST];
        A[mt][2] = ab[4];
        A[mt][3] = ab[8 * KST + 4];
      }
#pragma unroll
      for (int nt = 0; nt < 8; nt++) {
        const uint32_t* bb = Qsu + (wn + nt * 8 + qr) * QST + k0 + qc;
        uint32_t b0 = bb[0], b1 = bb[4];
        mma_tf32(S[0][nt], A[0], b0, b1);
        mma_tf32(S[1][nt], A[1], b0, b1);
      }
    }

    // ---- masked exp (no max), row-sum partials
    unsigned mw[4][2];
#pragma unroll
    for (int r = 0; r < 4; r++) {
      size_t base = (size_t)(i0 + wm + row_rel[r]) * (NSEQ / 32) + ((j0 + wn) >> 5);
      mw[r][0] = g_mbits[base];
      mw[r][1] = g_mbits[base + 1];
    }
    float lacc[4] = {0.f, 0.f, 0.f, 0.f};
#pragma unroll
    for (int mt = 0; mt < 2; mt++) {
#pragma unroll
      for (int nt = 0; nt < 8; nt++) {
        const int ws = nt >> 2;
        const int b0 = ((nt * 8) & 31) + 2 * qc;
        const unsigned w0 = mw[mt * 2][ws], w1 = mw[mt * 2 + 1][ws];
        float* s = S[mt][nt];
        float p0 = ((w0 >> b0) & 1u) ? __expf(s[0] * INV_SQRT_N) : 0.f;
        float p1 = ((w0 >> (b0 + 1)) & 1u) ? __expf(s[1] * INV_SQRT_N) : 0.f;
        float p2 = ((w1 >> b0) & 1u) ? __expf(s[2] * INV_SQRT_N) : 0.f;
        float p3 = ((w1 >> (b0 + 1)) & 1u) ? __expf(s[3] * INV_SQRT_N) : 0.f;
        s[0] = p0; s[1] = p1; s[2] = p2; s[3] = p3;
        lacc[mt * 2] += p0 + p1;
        lacc[mt * 2 + 1] += p2 + p3;
      }
    }
#pragma unroll
    for (int r = 0; r < 4; r++) {
      float v = lacc[r];
      v += __shfl_xor_sync(0xffffffffu, v, 1);
      v += __shfl_xor_sync(0xffffffffu, v, 2);
      L[r] += v;
    }

    __syncthreads();  // all warps done reading Qs -> safe to overwrite with P

    // ---- P -> smem (tf32), row-major [i][j], stride 132
#pragma unroll
    for (int mt = 0; mt < 2; mt++) {
#pragma unroll
      for (int nt = 0; nt < 8; nt++) {
        const int row0 = wm + mt * 16 + qr;
        const int col = wn + nt * 8 + 2 * qc;
        const float* s = S[mt][nt];
        uint2 p01 = make_uint2(f2tf(s[0]), f2tf(s[1]));
        uint2 p23 = make_uint2(f2tf(s[2]), f2tf(s[3]));
        *reinterpret_cast<uint2*>(Qsu + row0 * QST + col) = p01;
        *reinterpret_cast<uint2*>(Qsu + (row0 + 8) * QST + col) = p23;
      }
    }
    __syncthreads();

    // ---- O += P · V  (m=i 32, n=d 64, k=j 128)
#pragma unroll 4
    for (int k0 = 0; k0 < 128; k0 += 8) {
      uint32_t A[2][4];
#pragma unroll
      for (int mt = 0; mt < 2; mt++) {
        const uint32_t* ab = Qsu + (wm + mt * 16 + qr) * QST + k0 + qc;
        A[mt][0] = ab[0];
        A[mt][1] = ab[8 * QST];
        A[mt][2] = ab[4];
        A[mt][3] = ab[8 * QST + 4];
      }
#pragma unroll
      for (int nt = 0; nt < 8; nt++) {
        const int d = wn + nt * 8 + qr;
        uint32_t b0 = Vsu[(k0 + qc) * VST + d];
        uint32_t b1 = Vsu[(k0 + qc + 4) * VST + d];
        mma_tf32(O[0][nt], A[0], b0, b1);
        mma_tf32(O[1][nt], A[1], b0, b1);
      }
    }
  }

  // ---- combine row sums across the two n-half warps
  if (qc == 0) {
#pragma unroll
    for (int r = 0; r < 4; r++)
      l_sh[(wid >> 2) * 128 + wm + row_rel[r]] = L[r];
  }
  __syncthreads();
  float linv[4];
#pragma unroll
  for (int r = 0; r < 4; r++) {
    int row = wm + row_rel[r];
    linv[r] = 1.f / (l_sh[row] + l_sh[128 + row]);
  }

  // ---- epilogue: normalize & write ctx[n][h*128+d]
#pragma unroll
  for (int mt = 0; mt < 2; mt++) {
#pragma unroll
    for (int nt = 0; nt < 8; nt++) {
      const int row0 = wm + mt * 16 + qr;
      const int col = h * DIMD + wn + nt * 8 + 2 * qc;
      const float* o = O[mt][nt];
      float2 a = make_float2(o[0] * linv[mt * 2], o[1] * linv[mt * 2]);
      float2 b = make_float2(o[2] * linv[mt * 2 + 1], o[3] * linv[mt * 2 + 1]);
      *reinterpret_cast<float2*>(g_ctx + (size_t)(i0 + row0) * (HEADS * DIMD) + col) = a;
      *reinterpret_cast<float2*>(g_ctx + (size_t)(i0 + row0 + 8) * (HEADS * DIMD) + col) = b;
    }
  }
}

// ======================= kernel 3: out = ctx @ last (fp32) ==================
__global__ void __launch_bounds__(256) out_kernel(const float* __restrict__ last,
                                                  float* __restrict__ out) {
  __shared__ float As[32][68];
  __shared__ float Bs[64][132];
  const int n0 = blockIdx.x * 32;
  const int tid = threadIdx.x;
  const int ty = tid >> 5, tx = tid & 31;
  const int r0 = ty * 4, c0 = tx * 4;

  float acc[4][4];
#pragma unroll
  for (int i = 0; i < 4; i++)
#pragma unroll
    for (int j = 0; j < 4; j++) acc[i][j] = 0.f;

  for (int k0 = 0; k0 < HEADS * DIMD; k0 += 64) {
    __syncthreads();
    for (int idx = tid; idx < 32 * 16; idx += 256) {
      int r = idx >> 4, c4 = (idx & 15) * 4;
      *reinterpret_cast<float4*>(&As[r][c4]) = *reinterpret_cast<const float4*>(
          g_ctx + (size_t)(n0 + r) * (HEADS * DIMD) + k0 + c4);
    }
    for (int idx = tid; idx < 64 * 32; idx += 256) {
      int kk = idx >> 5, e4 = (idx & 31) * 4;
      *reinterpret_cast<float4*>(&Bs[kk][e4]) =
          *reinterpret_cast<const float4*>(last + (size_t)(k0 + kk) * DIMD + e4);
    }
    __syncthreads();
#pragma unroll 4
    for (int kk = 0; kk < 64; kk++) {
      float4 b = *reinterpret_cast<const float4*>(&Bs[kk][c0]);
      float a0 = As[r0][kk], a1 = As[r0 + 1][kk], a2 = As[r0 + 2][kk], a3 = As[r0 + 3][kk];
      acc[0][0] = fmaf(a0, b.x, acc[0][0]); acc[0][1] = fmaf(a0, b.y, acc[0][1]);
      acc[0][2] = fmaf(a0, b.z, acc[0][2]); acc[0][3] = fmaf(a0, b.w, acc[0][3]);
      acc[1][0] = fmaf(a1, b.x, acc[1][0]); acc[1][1] = fmaf(a1, b.y, acc[1][1]);
      acc[1][2] = fmaf(a1, b.z, acc[1][2]); acc[1][3] = fmaf(a1, b.w, acc[1][3]);
      acc[2][0] = fmaf(a2, b.x, acc[2][0]); acc[2][1] = fmaf(a2, b.y, acc[2][1]);
      acc[2][2] = fmaf(a2, b.z, acc[2][2]); acc[2][3] = fmaf(a2, b.w, acc[2][3]);
      acc[3][0] = fmaf(a3, b.x, acc[3][0]); acc[3][1] = fmaf(a3, b.y, acc[3][1]);
      acc[3][2] = fmaf(a3, b.z, acc[3][2]); acc[3][3] = fmaf(a3, b.w, acc[3][3]);
    }
  }
#pragma unroll
  for (int i = 0; i < 4; i++) {
    float4 w = make_float4(acc[i][0], acc[i][1], acc[i][2], acc[i][3]);
    *reinterpret_cast<float4*>(out + (size_t)(n0 + r0 + i) * DIMD + c0) = w;
  }
}

// =====================================================================
extern "C" void kernel_launch(void* const* d_in, const int* in_sizes, int n_in,
                              void* d_out, int out_size) {
  int mi = -1;
  for (int i = 0; i < n_in; i++)
    if (in_sizes[i] == NSEQ * NSEQ) { mi = i; break; }
  if (mi < 0) mi = 3;

  const void* p[7];
  int np = 0;
  for (int i = 0; i < n_in && np < 7; i++) {
    if (i == mi) continue;
    p[np++] = d_in[i];
  }
  const float* q = (const float*)p[0];
  const float* k = (const float*)p[1];
  const float* v = (const float*)p[2];
  const float* Qw = (const float*)p[3];
  const float* Kw = (const float*)p[4];
  const float* Vw = (const float*)p[5];
  const float* last = (const float*)p[6];
  const int* mask = (const int*)d_in[mi];
  float* out = (float*)d_out;

  const int PROJ_SMEM = 2 * 128 * 132 * 4;
  const int ATTN_SMEM = ATTN_SMEM_FLOATS * 4;  // 205,824 B

  cudaFuncSetAttribute(proj_kernel, cudaFuncAttributeMaxDynamicSharedMemorySize, PROJ_SMEM);
  cudaFuncSetAttribute(attn_mma_kernel, cudaFuncAttributeMaxDynamicSharedMemorySize, ATTN_SMEM);

  maskbits_kernel<<<NSEQ * (NSEQ / 32) / 8, 256>>>(mask);
  proj_kernel<<<dim3(NSEQ / 128, HEADS, 3), 256, PROJ_SMEM>>>(q, k, v, Qw, Kw, Vw);
  attn_mma_kernel<<<dim3(NSEQ / 128, HEADS), 256, ATTN_SMEM>>>();
  out_kernel<<<NSEQ / 32, 256>>>(last, out);
}

// round 4
// speedup vs baseline: 4.1800x; 1.3252x over previous
#include <cuda_runtime.h>
#include <cstdint>

#define HEADS 16
#define DIMD 128
#define NSEQ 2048
#define INV_SQRT_N 0.02209708691207961f /* 1/sqrt(2048) */
#define KSPLIT 8

// ---------------- scratch (static device globals; no allocations) ----------------
__device__ __align__(16) float g_qp[HEADS * NSEQ * DIMD];
__device__ __align__(16) float g_kp[HEADS * NSEQ * DIMD];
__device__ __align__(16) float g_vp[HEADS * NSEQ * DIMD];
__device__ __align__(16) float g_ctx[NSEQ * HEADS * DIMD];
__device__ __align__(16) float g_part[KSPLIT * NSEQ * DIMD];
__device__ __align__(16) unsigned g_mbits[NSEQ * (NSEQ / 32)];

// ---------------- helpers ----------------
__device__ __forceinline__ uint32_t f2tf(float x) {
  uint32_t r;
  asm("cvt.rna.tf32.f32 %0, %1;" : "=r"(r) : "f"(x));
  return r;
}

__device__ __forceinline__ void mma_tf32(float c[4], const uint32_t a[4],
                                         uint32_t b0, uint32_t b1) {
  asm volatile(
      "mma.sync.aligned.m16n8k8.row.col.f32.tf32.tf32.f32 "
      "{%0,%1,%2,%3}, {%4,%5,%6,%7}, {%8,%9}, {%0,%1,%2,%3};"
      : "+f"(c[0]), "+f"(c[1]), "+f"(c[2]), "+f"(c[3])
      : "r"(a[0]), "r"(a[1]), "r"(a[2]), "r"(a[3]), "r"(b0), "r"(b1));
}

// ======================= kernel 0: pack mask into bits =======================
__global__ void __launch_bounds__(256) maskbits_kernel(const int* __restrict__ mask) {
  int w = blockIdx.x * 8 + (threadIdx.x >> 5);
  int lane = threadIdx.x & 31;
  int m = mask[(size_t)w * 32 + lane];
  unsigned bits = __ballot_sync(0xffffffffu, m != 0);
  if (lane == 0) g_mbits[w] = bits;
}

// ======================= kernel 1: projections (tf32 tensor) ==================
// C[n0:128, 0:128] = X[n0:128, :] @ W_h  (per head h, per q/k/v)
#define PST 132
__global__ void __launch_bounds__(256) proj_tc_kernel(
    const float* __restrict__ q, const float* __restrict__ k,
    const float* __restrict__ v, const float* __restrict__ Qw,
    const float* __restrict__ Kw, const float* __restrict__ Vw) {
  extern __shared__ float sm[];
  uint32_t* Xs = reinterpret_cast<uint32_t*>(sm);              // [n=128][d=128] st 132
  uint32_t* Ws = reinterpret_cast<uint32_t*>(sm + 128 * PST);  // [e=128][d=128] st 132 (W^T)

  const int which = blockIdx.z;
  const float* A = (which == 0) ? q : (which == 1) ? k : v;
  const float* W = (which == 0) ? Qw : (which == 1) ? Kw : Vw;
  float* C = (which == 0) ? g_qp : (which == 1) ? g_kp : g_vp;
  const int h = blockIdx.y;
  const int n0 = blockIdx.x * 128;
  const int tid = threadIdx.x;
  const int wid = tid >> 5;
  const int lane = tid & 31;
  const int qr = lane >> 2, qc = lane & 3;
  const int wm = (wid & 3) * 32;
  const int wn = (wid >> 2) * 64;

  // X natural [n][d]
  for (int idx = tid; idx < 128 * 32; idx += 256) {
    int r = idx >> 5, c4 = (idx & 31) << 2;
    float4 t = *reinterpret_cast<const float4*>(A + (size_t)(n0 + r) * DIMD + c4);
    uint4 u = make_uint4(f2tf(t.x), f2tf(t.y), f2tf(t.z), f2tf(t.w));
    *reinterpret_cast<uint4*>(Xs + r * PST + c4) = u;
  }
  // W^T: thread (e = idx&127, d4 = (idx>>7)*4). Coalesced gmem, conflict-free STS.
  const float* Wh = W + (size_t)h * DIMD * DIMD;
  for (int idx = tid; idx < 128 * 32; idx += 256) {
    int e = idx & 127, d4 = (idx >> 7) << 2;
    uint4 u = make_uint4(f2tf(Wh[(d4 + 0) * DIMD + e]), f2tf(Wh[(d4 + 1) * DIMD + e]),
                         f2tf(Wh[(d4 + 2) * DIMD + e]), f2tf(Wh[(d4 + 3) * DIMD + e]));
    *reinterpret_cast<uint4*>(Ws + e * PST + d4) = u;
  }
  __syncthreads();

  float O[2][8][4];
#pragma unroll
  for (int mt = 0; mt < 2; mt++)
#pragma unroll
    for (int nt = 0; nt < 8; nt++)
#pragma unroll
      for (int e = 0; e < 4; e++) O[mt][nt][e] = 0.f;

#pragma unroll 4
  for (int k0 = 0; k0 < 128; k0 += 8) {
    uint32_t Af[2][4];
#pragma unroll
    for (int mt = 0; mt < 2; mt++) {
      const uint32_t* ab = Xs + (wm + mt * 16 + qr) * PST + k0 + qc;
      Af[mt][0] = ab[0];
      Af[mt][1] = ab[8 * PST];
      Af[mt][2] = ab[4];
      Af[mt][3] = ab[8 * PST + 4];
    }
#pragma unroll
    for (int nt = 0; nt < 8; nt++) {
      const uint32_t* bb = Ws + (wn + nt * 8 + qr) * PST + k0 + qc;
      uint32_t b0 = bb[0], b1 = bb[4];
      mma_tf32(O[0][nt], Af[0], b0, b1);
      mma_tf32(O[1][nt], Af[1], b0, b1);
    }
  }

  float* Cb = C + ((size_t)h * NSEQ + n0) * DIMD;
#pragma unroll
  for (int mt = 0; mt < 2; mt++) {
#pragma unroll
    for (int nt = 0; nt < 8; nt++) {
      const int row0 = wm + mt * 16 + qr;
      const int col = wn + nt * 8 + 2 * qc;
      const float* o = O[mt][nt];
      *reinterpret_cast<float2*>(Cb + (size_t)row0 * DIMD + col) = make_float2(o[0], o[1]);
      *reinterpret_cast<float2*>(Cb + (size_t)(row0 + 8) * DIMD + col) = make_float2(o[2], o[3]);
    }
  }
}

// ======================= kernel 2: mma.sync tf32 attention ===================
#define KST 132
#define QST 132
#define VST 136
#define SM_K 0
#define SM_Q (128 * KST)
#define SM_V (2 * 128 * 132)
#define SM_L (2 * 128 * 132 + 128 * VST)
#define ATTN_SMEM_FLOATS (2 * 128 * 132 + 128 * VST + 256)

__global__ void __launch_bounds__(256) attn_mma_kernel() {
  extern __shared__ float sm[];
  uint32_t* Ksu = reinterpret_cast<uint32_t*>(sm + SM_K);
  uint32_t* Qsu = reinterpret_cast<uint32_t*>(sm + SM_Q);  // also holds P
  uint32_t* Vsu = reinterpret_cast<uint32_t*>(sm + SM_V);
  float* l_sh = sm + SM_L;  // [2][128]

  const int tid = threadIdx.x;
  const int wid = tid >> 5;
  const int lane = tid & 31;
  const int qr = lane >> 2;
  const int qc = lane & 3;
  const int wm = (wid & 3) * 32;
  const int wn = (wid >> 2) * 64;

  const int h = blockIdx.y;
  const int i0 = blockIdx.x * 128;

  const float* kp = g_kp + (size_t)h * NSEQ * DIMD;
  const float* qp = g_qp + (size_t)h * NSEQ * DIMD;
  const float* vp = g_vp + (size_t)h * NSEQ * DIMD;

  for (int idx = tid; idx < 128 * 32; idx += 256) {
    int r = idx >> 5, c4 = (idx & 31) << 2;
    float4 t = *reinterpret_cast<const float4*>(kp + (size_t)(i0 + r) * DIMD + c4);
    uint4 u = make_uint4(f2tf(t.x), f2tf(t.y), f2tf(t.z), f2tf(t.w));
    *reinterpret_cast<uint4*>(Ksu + r * KST + c4) = u;
  }

  float O[2][8][4];
#pragma unroll
  for (int mt = 0; mt < 2; mt++)
#pragma unroll
    for (int nt = 0; nt < 8; nt++)
#pragma unroll
      for (int e = 0; e < 4; e++) O[mt][nt][e] = 0.f;
  float L[4] = {0.f, 0.f, 0.f, 0.f};

  const int row_rel[4] = {qr, qr + 8, qr + 16, qr + 24};

  for (int jt = 0; jt < NSEQ / 128; jt++) {
    const int j0 = jt * 128;
    __syncthreads();

    for (int idx = tid; idx < 128 * 32; idx += 256) {
      int r = idx >> 5, c4 = (idx & 31) << 2;
      float4 t = *reinterpret_cast<const float4*>(qp + (size_t)(j0 + r) * DIMD + c4);
      uint4 u = make_uint4(f2tf(t.x), f2tf(t.y), f2tf(t.z), f2tf(t.w));
      *reinterpret_cast<uint4*>(Qsu + r * QST + c4) = u;
      float4 tv = *reinterpret_cast<const float4*>(vp + (size_t)(j0 + r) * DIMD + c4);
      uint4 uv = make_uint4(f2tf(tv.x), f2tf(tv.y), f2tf(tv.z), f2tf(tv.w));
      *reinterpret_cast<uint4*>(Vsu + r * VST + c4) = uv;
    }
    __syncthreads();

    float S[2][8][4];
#pragma unroll
    for (int mt = 0; mt < 2; mt++)
#pragma unroll
      for (int nt = 0; nt < 8; nt++)
#pragma unroll
        for (int e = 0; e < 4; e++) S[mt][nt][e] = 0.f;

#pragma unroll 4
    for (int k0 = 0; k0 < 128; k0 += 8) {
      uint32_t A[2][4];
#pragma unroll
      for (int mt = 0; mt < 2; mt++) {
        const uint32_t* ab = Ksu + (wm + mt * 16 + qr) * KST + k0 + qc;
        A[mt][0] = ab[0];
        A[mt][1] = ab[8 * KST];
        A[mt][2] = ab[4];
        A[mt][3] = ab[8 * KST + 4];
      }
#pragma unroll
      for (int nt = 0; nt < 8; nt++) {
        const uint32_t* bb = Qsu + (wn + nt * 8 + qr) * QST + k0 + qc;
        uint32_t b0 = bb[0], b1 = bb[4];
        mma_tf32(S[0][nt], A[0], b0, b1);
        mma_tf32(S[1][nt], A[1], b0, b1);
      }
    }

    unsigned mw[4][2];
#pragma unroll
    for (int r = 0; r < 4; r++) {
      size_t base = (size_t)(i0 + wm + row_rel[r]) * (NSEQ / 32) + ((j0 + wn) >> 5);
      mw[r][0] = g_mbits[base];
      mw[r][1] = g_mbits[base + 1];
    }
    float lacc[4] = {0.f, 0.f, 0.f, 0.f};
#pragma unroll
    for (int mt = 0; mt < 2; mt++) {
#pragma unroll
      for (int nt = 0; nt < 8; nt++) {
        const int ws = nt >> 2;
        const int b0 = ((nt * 8) & 31) + 2 * qc;
        const unsigned w0 = mw[mt * 2][ws], w1 = mw[mt * 2 + 1][ws];
        float* s = S[mt][nt];
        float p0 = ((w0 >> b0) & 1u) ? __expf(s[0] * INV_SQRT_N) : 0.f;
        float p1 = ((w0 >> (b0 + 1)) & 1u) ? __expf(s[1] * INV_SQRT_N) : 0.f;
        float p2 = ((w1 >> b0) & 1u) ? __expf(s[2] * INV_SQRT_N) : 0.f;
        float p3 = ((w1 >> (b0 + 1)) & 1u) ? __expf(s[3] * INV_SQRT_N) : 0.f;
        s[0] = p0; s[1] = p1; s[2] = p2; s[3] = p3;
        lacc[mt * 2] += p0 + p1;
        lacc[mt * 2 + 1] += p2 + p3;
      }
    }
#pragma unroll
    for (int r = 0; r < 4; r++) {
      float v = lacc[r];
      v += __shfl_xor_sync(0xffffffffu, v, 1);
      v += __shfl_xor_sync(0xffffffffu, v, 2);
      L[r] += v;
    }

    __syncthreads();

#pragma unroll
    for (int mt = 0; mt < 2; mt++) {
#pragma unroll
      for (int nt = 0; nt < 8; nt++) {
        const int row0 = wm + mt * 16 + qr;
        const int col = wn + nt * 8 + 2 * qc;
        const float* s = S[mt][nt];
        uint2 p01 = make_uint2(f2tf(s[0]), f2tf(s[1]));
        uint2 p23 = make_uint2(f2tf(s[2]), f2tf(s[3]));
        *reinterpret_cast<uint2*>(Qsu + row0 * QST + col) = p01;
        *reinterpret_cast<uint2*>(Qsu + (row0 + 8) * QST + col) = p23;
      }
    }
    __syncthreads();

#pragma unroll 4
    for (int k0 = 0; k0 < 128; k0 += 8) {
      uint32_t A[2][4];
#pragma unroll
      for (int mt = 0; mt < 2; mt++) {
        const uint32_t* ab = Qsu + (wm + mt * 16 + qr) * QST + k0 + qc;
        A[mt][0] = ab[0];
        A[mt][1] = ab[8 * QST];
        A[mt][2] = ab[4];
        A[mt][3] = ab[8 * QST + 4];
      }
#pragma unroll
      for (int nt = 0; nt < 8; nt++) {
        const int d = wn + nt * 8 + qr;
        uint32_t b0 = Vsu[(k0 + qc) * VST + d];
        uint32_t b1 = Vsu[(k0 + qc + 4) * VST + d];
        mma_tf32(O[0][nt], A[0], b0, b1);
        mma_tf32(O[1][nt], A[1], b0, b1);
      }
    }
  }

  if (qc == 0) {
#pragma unroll
    for (int r = 0; r < 4; r++)
      l_sh[(wid >> 2) * 128 + wm + row_rel[r]] = L[r];
  }
  __syncthreads();
  float linv[4];
#pragma unroll
  for (int r = 0; r < 4; r++) {
    int row = wm + row_rel[r];
    linv[r] = 1.f / (l_sh[row] + l_sh[128 + row]);
  }

#pragma unroll
  for (int mt = 0; mt < 2; mt++) {
#pragma unroll
    for (int nt = 0; nt < 8; nt++) {
      const int row0 = wm + mt * 16 + qr;
      const int col = h * DIMD + wn + nt * 8 + 2 * qc;
      const float* o = O[mt][nt];
      float2 a = make_float2(o[0] * linv[mt * 2], o[1] * linv[mt * 2]);
      float2 b = make_float2(o[2] * linv[mt * 2 + 1], o[3] * linv[mt * 2 + 1]);
      *reinterpret_cast<float2*>(g_ctx + (size_t)(i0 + row0) * (HEADS * DIMD) + col) = a;
      *reinterpret_cast<float2*>(g_ctx + (size_t)(i0 + row0 + 8) * (HEADS * DIMD) + col) = b;
    }
  }
}

// ======================= kernel 3: out (tf32 tensor, split-K) ==================
// grid (16 m-tiles, 8 k-chunks of 256). Partial[kc] = ctx[m0:128, kb:kb+256] @ last[kb:kb+256, :]
__global__ void __launch_bounds__(256) out_tc_kernel(const float* __restrict__ last) {
  extern __shared__ float sm[];
  uint32_t* Xs = reinterpret_cast<uint32_t*>(sm);              // [m=128][k=128] st 132
  uint32_t* Bt = reinterpret_cast<uint32_t*>(sm + 128 * PST);  // [e=128][k=128] st 132

  const int m0 = blockIdx.x * 128;
  const int kc = blockIdx.y;
  const int tid = threadIdx.x;
  const int wid = tid >> 5;
  const int lane = tid & 31;
  const int qr = lane >> 2, qc = lane & 3;
  const int wm = (wid & 3) * 32;
  const int wn = (wid >> 2) * 64;

  float O[2][8][4];
#pragma unroll
  for (int mt = 0; mt < 2; mt++)
#pragma unroll
    for (int nt = 0; nt < 8; nt++)
#pragma unroll
      for (int e = 0; e < 4; e++) O[mt][nt][e] = 0.f;

  for (int ks = 0; ks < 2; ks++) {
    const int kb = kc * 256 + ks * 128;
    __syncthreads();
    for (int idx = tid; idx < 128 * 32; idx += 256) {
      int r = idx >> 5, c4 = (idx & 31) << 2;
      float4 t = *reinterpret_cast<const float4*>(
          g_ctx + (size_t)(m0 + r) * (HEADS * DIMD) + kb + c4);
      uint4 u = make_uint4(f2tf(t.x), f2tf(t.y), f2tf(t.z), f2tf(t.w));
      *reinterpret_cast<uint4*>(Xs + r * PST + c4) = u;
    }
    for (int idx = tid; idx < 128 * 32; idx += 256) {
      int e = idx & 127, k4 = (idx >> 7) << 2;
      uint4 u = make_uint4(f2tf(last[(size_t)(kb + k4 + 0) * DIMD + e]),
                           f2tf(last[(size_t)(kb + k4 + 1) * DIMD + e]),
                           f2tf(last[(size_t)(kb + k4 + 2) * DIMD + e]),
                           f2tf(last[(size_t)(kb + k4 + 3) * DIMD + e]));
      *reinterpret_cast<uint4*>(Bt + e * PST + k4) = u;
    }
    __syncthreads();

#pragma unroll 4
    for (int k0 = 0; k0 < 128; k0 += 8) {
      uint32_t Af[2][4];
#pragma unroll
      for (int mt = 0; mt < 2; mt++) {
        const uint32_t* ab = Xs + (wm + mt * 16 + qr) * PST + k0 + qc;
        Af[mt][0] = ab[0];
        Af[mt][1] = ab[8 * PST];
        Af[mt][2] = ab[4];
        Af[mt][3] = ab[8 * PST + 4];
      }
#pragma unroll
      for (int nt = 0; nt < 8; nt++) {
        const uint32_t* bb = Bt + (wn + nt * 8 + qr) * PST + k0 + qc;
        uint32_t b0 = bb[0], b1 = bb[4];
        mma_tf32(O[0][nt], Af[0], b0, b1);
        mma_tf32(O[1][nt], Af[1], b0, b1);
      }
    }
  }

  float* Pb = g_part + (size_t)kc * NSEQ * DIMD + (size_t)m0 * DIMD;
#pragma unroll
  for (int mt = 0; mt < 2; mt++) {
#pragma unroll
    for (int nt = 0; nt < 8; nt++) {
      const int row0 = wm + mt * 16 + qr;
      const int col = wn + nt * 8 + 2 * qc;
      const float* o = O[mt][nt];
      *reinterpret_cast<float2*>(Pb + (size_t)row0 * DIMD + col) = make_float2(o[0], o[1]);
      *reinterpret_cast<float2*>(Pb + (size_t)(row0 + 8) * DIMD + col) = make_float2(o[2], o[3]);
    }
  }
}

// deterministic split-K reduce: out = sum_kc partial[kc]
__global__ void __launch_bounds__(256) reduce_kernel(float* __restrict__ out) {
  int i = blockIdx.x * 256 + threadIdx.x;  // float4 index, 65536 total
  const float4* p = reinterpret_cast<const float4*>(g_part);
  float4 a = p[i];
#pragma unroll
  for (int kc = 1; kc < KSPLIT; kc++) {
    float4 b = p[(size_t)kc * (NSEQ * DIMD / 4) + i];
    a.x += b.x; a.y += b.y; a.z += b.z; a.w += b.w;
  }
  reinterpret_cast<float4*>(out)[i] = a;
}

// =====================================================================
extern "C" void kernel_launch(void* const* d_in, const int* in_sizes, int n_in,
                              void* d_out, int out_size) {
  int mi = -1;
  for (int i = 0; i < n_in; i++)
    if (in_sizes[i] == NSEQ * NSEQ) { mi = i; break; }
  if (mi < 0) mi = 3;

  const void* p[7];
  int np = 0;
  for (int i = 0; i < n_in && np < 7; i++) {
    if (i == mi) continue;
    p[np++] = d_in[i];
  }
  const float* q = (const float*)p[0];
  const float* k = (const float*)p[1];
  const float* v = (const float*)p[2];
  const float* Qw = (const float*)p[3];
  const float* Kw = (const float*)p[4];
  const float* Vw = (const float*)p[5];
  const float* last = (const float*)p[6];
  const int* mask = (const int*)d_in[mi];
  float* out = (float*)d_out;

  const int GEMM_SMEM = 2 * 128 * PST * 4;      // 135,168 B
  const int ATTN_SMEM = ATTN_SMEM_FLOATS * 4;   // 205,824 B

  cudaFuncSetAttribute(proj_tc_kernel, cudaFuncAttributeMaxDynamicSharedMemorySize, GEMM_SMEM);
  cudaFuncSetAttribute(out_tc_kernel, cudaFuncAttributeMaxDynamicSharedMemorySize, GEMM_SMEM);
  cudaFuncSetAttribute(attn_mma_kernel, cudaFuncAttributeMaxDynamicSharedMemorySize, ATTN_SMEM);

  maskbits_kernel<<<NSEQ * (NSEQ / 32) / 8, 256>>>(mask);
  proj_tc_kernel<<<dim3(NSEQ / 128, HEADS, 3), 256, GEMM_SMEM>>>(q, k, v, Qw, Kw, Vw);
  attn_mma_kernel<<<dim3(NSEQ / 128, HEADS), 256, ATTN_SMEM>>>();
  out_tc_kernel<<<dim3(NSEQ / 128, KSPLIT), 256, GEMM_SMEM>>>(last);
  reduce_kernel<<<NSEQ * DIMD / 4 / 256, 256>>>(out);
}

// round 5
// speedup vs baseline: 4.2552x; 1.0180x over previous
#include <cuda_runtime.h>
#include <cstdint>

#define HEADS 16
#define DIMD 128
#define NSEQ 2048
#define INV_SQRT_N 0.02209708691207961f /* 1/sqrt(2048) */
#define KSPLIT 8

// ---------------- scratch (static device globals; no allocations) ----------------
__device__ __align__(16) float g_qp[HEADS * NSEQ * DIMD];
__device__ __align__(16) float g_kp[HEADS * NSEQ * DIMD];
__device__ __align__(16) float g_vp[HEADS * NSEQ * DIMD];
__device__ __align__(16) float g_ctx[NSEQ * HEADS * DIMD];
__device__ __align__(16) float g_part[KSPLIT * NSEQ * DIMD];
__device__ __align__(16) unsigned g_mbits[NSEQ * (NSEQ / 32)];

// ---------------- helpers ----------------
__device__ __forceinline__ uint32_t f2tf(float x) {
  uint32_t r;
  asm("cvt.rna.tf32.f32 %0, %1;" : "=r"(r) : "f"(x));
  return r;
}

__device__ __forceinline__ void mma_tf32(float c[4], const uint32_t a[4],
                                         uint32_t b0, uint32_t b1) {
  asm volatile(
      "mma.sync.aligned.m16n8k8.row.col.f32.tf32.tf32.f32 "
      "{%0,%1,%2,%3}, {%4,%5,%6,%7}, {%8,%9}, {%0,%1,%2,%3};"
      : "+f"(c[0]), "+f"(c[1]), "+f"(c[2]), "+f"(c[3])
      : "r"(a[0]), "r"(a[1]), "r"(a[2]), "r"(a[3]), "r"(b0), "r"(b1));
}

// ======================= kernel 0: pack mask into bits =======================
__global__ void __launch_bounds__(256) maskbits_kernel(const int* __restrict__ mask) {
  int w = blockIdx.x * 8 + (threadIdx.x >> 5);
  int lane = threadIdx.x & 31;
  int m = mask[(size_t)w * 32 + lane];
  unsigned bits = __ballot_sync(0xffffffffu, m != 0);
  if (lane == 0) g_mbits[w] = bits;
}

// ======================= kernel 1: projections (tf32 tensor) ==================
#define PST 132
__global__ void __launch_bounds__(256) proj_tc_kernel(
    const float* __restrict__ q, const float* __restrict__ k,
    const float* __restrict__ v, const float* __restrict__ Qw,
    const float* __restrict__ Kw, const float* __restrict__ Vw) {
  extern __shared__ float sm[];
  uint32_t* Xs = reinterpret_cast<uint32_t*>(sm);              // [n=128][d=128] st 132
  uint32_t* Ws = reinterpret_cast<uint32_t*>(sm + 128 * PST);  // [e=128][d=128] st 132 (W^T)

  const int which = blockIdx.z;
  const float* A = (which == 0) ? q : (which == 1) ? k : v;
  const float* W = (which == 0) ? Qw : (which == 1) ? Kw : Vw;
  float* C = (which == 0) ? g_qp : (which == 1) ? g_kp : g_vp;
  const int h = blockIdx.y;
  const int n0 = blockIdx.x * 128;
  const int tid = threadIdx.x;
  const int wid = tid >> 5;
  const int lane = tid & 31;
  const int qr = lane >> 2, qc = lane & 3;
  const int wm = (wid & 3) * 32;
  const int wn = (wid >> 2) * 64;

  for (int idx = tid; idx < 128 * 32; idx += 256) {
    int r = idx >> 5, c4 = (idx & 31) << 2;
    float4 t = *reinterpret_cast<const float4*>(A + (size_t)(n0 + r) * DIMD + c4);
    uint4 u = make_uint4(f2tf(t.x), f2tf(t.y), f2tf(t.z), f2tf(t.w));
    *reinterpret_cast<uint4*>(Xs + r * PST + c4) = u;
  }
  const float* Wh = W + (size_t)h * DIMD * DIMD;
  for (int idx = tid; idx < 128 * 32; idx += 256) {
    int e = idx & 127, d4 = (idx >> 7) << 2;
    uint4 u = make_uint4(f2tf(Wh[(d4 + 0) * DIMD + e]), f2tf(Wh[(d4 + 1) * DIMD + e]),
                         f2tf(Wh[(d4 + 2) * DIMD + e]), f2tf(Wh[(d4 + 3) * DIMD + e]));
    *reinterpret_cast<uint4*>(Ws + e * PST + d4) = u;
  }
  __syncthreads();

  float O[2][8][4];
#pragma unroll
  for (int mt = 0; mt < 2; mt++)
#pragma unroll
    for (int nt = 0; nt < 8; nt++)
#pragma unroll
      for (int e = 0; e < 4; e++) O[mt][nt][e] = 0.f;

#pragma unroll 4
  for (int k0 = 0; k0 < 128; k0 += 8) {
    uint32_t Af[2][4];
#pragma unroll
    for (int mt = 0; mt < 2; mt++) {
      const uint32_t* ab = Xs + (wm + mt * 16 + qr) * PST + k0 + qc;
      Af[mt][0] = ab[0];
      Af[mt][1] = ab[8 * PST];
      Af[mt][2] = ab[4];
      Af[mt][3] = ab[8 * PST + 4];
    }
#pragma unroll
    for (int nt = 0; nt < 8; nt++) {
      const uint32_t* bb = Ws + (wn + nt * 8 + qr) * PST + k0 + qc;
      uint32_t b0 = bb[0], b1 = bb[4];
      mma_tf32(O[0][nt], Af[0], b0, b1);
      mma_tf32(O[1][nt], Af[1], b0, b1);
    }
  }

  float* Cb = C + ((size_t)h * NSEQ + n0) * DIMD;
#pragma unroll
  for (int mt = 0; mt < 2; mt++) {
#pragma unroll
    for (int nt = 0; nt < 8; nt++) {
      const int row0 = wm + mt * 16 + qr;
      const int col = wn + nt * 8 + 2 * qc;
      const float* o = O[mt][nt];
      *reinterpret_cast<float2*>(Cb + (size_t)row0 * DIMD + col) = make_float2(o[0], o[1]);
      *reinterpret_cast<float2*>(Cb + (size_t)(row0 + 8) * DIMD + col) = make_float2(o[2], o[3]);
    }
  }
}

// ======================= kernel 2: mma.sync tf32 attention (512 thr) =========
// Block: one head h, 128 K-rows. 16 warps, warp grid 4m x 4n (32x32 tiles).
// Q tile for the next iteration is prefetched into registers so LDG latency
// overlaps the S-phase MMAs.
#define KST 132
#define QST 132
#define VST 136
#define SM_K 0
#define SM_Q (128 * KST)
#define SM_V (2 * 128 * 132)
#define SM_L (2 * 128 * 132 + 128 * VST)
#define ATTN_SMEM_FLOATS (2 * 128 * 132 + 128 * VST + 512)

__global__ void __launch_bounds__(512) attn_mma_kernel() {
  extern __shared__ float sm[];
  uint32_t* Ksu = reinterpret_cast<uint32_t*>(sm + SM_K);
  uint32_t* Qsu = reinterpret_cast<uint32_t*>(sm + SM_Q);  // also holds P
  uint32_t* Vsu = reinterpret_cast<uint32_t*>(sm + SM_V);
  float* l_sh = sm + SM_L;  // [4][128]

  const int tid = threadIdx.x;
  const int wid = tid >> 5;
  const int lane = tid & 31;
  const int qr = lane >> 2;
  const int qc = lane & 3;
  const int wm = (wid & 3) * 32;
  const int wn = (wid >> 2) * 32;

  const int h = blockIdx.y;
  const int i0 = blockIdx.x * 128;

  const float* kp = g_kp + (size_t)h * NSEQ * DIMD;
  const float* qp = g_qp + (size_t)h * NSEQ * DIMD;
  const float* vp = g_vp + (size_t)h * NSEQ * DIMD;

  // K tile (persistent)
  for (int idx = tid; idx < 128 * 32; idx += 512) {
    int r = idx >> 5, c4 = (idx & 31) << 2;
    float4 t = *reinterpret_cast<const float4*>(kp + (size_t)(i0 + r) * DIMD + c4);
    uint4 u = make_uint4(f2tf(t.x), f2tf(t.y), f2tf(t.z), f2tf(t.w));
    *reinterpret_cast<uint4*>(Ksu + r * KST + c4) = u;
  }

  // prefetch Q tile 0 into regs (8 x float4 per thread)
  float4 qpre[8];
#pragma unroll
  for (int p = 0; p < 8; p++) {
    int idx = tid + p * 512;
    int r = idx >> 5, c4 = (idx & 31) << 2;
    qpre[p] = *reinterpret_cast<const float4*>(qp + (size_t)r * DIMD + c4);
  }

  float O[2][4][4];
#pragma unroll
  for (int mt = 0; mt < 2; mt++)
#pragma unroll
    for (int nt = 0; nt < 4; nt++)
#pragma unroll
      for (int e = 0; e < 4; e++) O[mt][nt][e] = 0.f;
  float L[4] = {0.f, 0.f, 0.f, 0.f};

  const int row_rel[4] = {qr, qr + 8, qr + 16, qr + 24};

  for (int jt = 0; jt < NSEQ / 128; jt++) {
    const int j0 = jt * 128;
    __syncthreads();  // prev PV done reading Qs(P) and Vs

    // STS prefetched Q; LDG+STS V for current tile
#pragma unroll
    for (int p = 0; p < 8; p++) {
      int idx = tid + p * 512;
      int r = idx >> 5, c4 = (idx & 31) << 2;
      float4 t = qpre[p];
      *reinterpret_cast<uint4*>(Qsu + r * QST + c4) =
          make_uint4(f2tf(t.x), f2tf(t.y), f2tf(t.z), f2tf(t.w));
      float4 tv = *reinterpret_cast<const float4*>(vp + (size_t)(j0 + r) * DIMD + c4);
      *reinterpret_cast<uint4*>(Vsu + r * VST + c4) =
          make_uint4(f2tf(tv.x), f2tf(tv.y), f2tf(tv.z), f2tf(tv.w));
    }
    // prefetch next Q tile (overlaps S-phase)
    if (jt < NSEQ / 128 - 1) {
      const int jn = j0 + 128;
#pragma unroll
      for (int p = 0; p < 8; p++) {
        int idx = tid + p * 512;
        int r = idx >> 5, c4 = (idx & 31) << 2;
        qpre[p] = *reinterpret_cast<const float4*>(qp + (size_t)(jn + r) * DIMD + c4);
      }
    }
    __syncthreads();

    // ---- S = K · Q^T  (warp: 32m x 32n)
    float S[2][4][4];
#pragma unroll
    for (int mt = 0; mt < 2; mt++)
#pragma unroll
      for (int nt = 0; nt < 4; nt++)
#pragma unroll
        for (int e = 0; e < 4; e++) S[mt][nt][e] = 0.f;

#pragma unroll 4
    for (int k0 = 0; k0 < 128; k0 += 8) {
      uint32_t A[2][4];
#pragma unroll
      for (int mt = 0; mt < 2; mt++) {
        const uint32_t* ab = Ksu + (wm + mt * 16 + qr) * KST + k0 + qc;
        A[mt][0] = ab[0];
        A[mt][1] = ab[8 * KST];
        A[mt][2] = ab[4];
        A[mt][3] = ab[8 * KST + 4];
      }
#pragma unroll
      for (int nt = 0; nt < 4; nt++) {
        const uint32_t* bb = Qsu + (wn + nt * 8 + qr) * QST + k0 + qc;
        uint32_t b0 = bb[0], b1 = bb[4];
        mma_tf32(S[0][nt], A[0], b0, b1);
        mma_tf32(S[1][nt], A[1], b0, b1);
      }
    }

    // ---- masked exp (no max): warp's 32 cols = one mask word per row
    unsigned mw[4];
#pragma unroll
    for (int r = 0; r < 4; r++)
      mw[r] = g_mbits[(size_t)(i0 + wm + row_rel[r]) * (NSEQ / 32) + ((j0 + wn) >> 5)];

    float lacc[4] = {0.f, 0.f, 0.f, 0.f};
#pragma unroll
    for (int mt = 0; mt < 2; mt++) {
#pragma unroll
      for (int nt = 0; nt < 4; nt++) {
        const int b0 = nt * 8 + 2 * qc;
        const unsigned w0 = mw[mt * 2], w1 = mw[mt * 2 + 1];
        float* s = S[mt][nt];
        float p0 = ((w0 >> b0) & 1u) ? __expf(s[0] * INV_SQRT_N) : 0.f;
        float p1 = ((w0 >> (b0 + 1)) & 1u) ? __expf(s[1] * INV_SQRT_N) : 0.f;
        float p2 = ((w1 >> b0) & 1u) ? __expf(s[2] * INV_SQRT_N) : 0.f;
        float p3 = ((w1 >> (b0 + 1)) & 1u) ? __expf(s[3] * INV_SQRT_N) : 0.f;
        s[0] = p0; s[1] = p1; s[2] = p2; s[3] = p3;
        lacc[mt * 2] += p0 + p1;
        lacc[mt * 2 + 1] += p2 + p3;
      }
    }
#pragma unroll
    for (int r = 0; r < 4; r++) {
      float v = lacc[r];
      v += __shfl_xor_sync(0xffffffffu, v, 1);
      v += __shfl_xor_sync(0xffffffffu, v, 2);
      L[r] += v;
    }

    __syncthreads();  // all warps done reading Qs -> overwrite with P

#pragma unroll
    for (int mt = 0; mt < 2; mt++) {
#pragma unroll
      for (int nt = 0; nt < 4; nt++) {
        const int row0 = wm + mt * 16 + qr;
        const int col = wn + nt * 8 + 2 * qc;
        const float* s = S[mt][nt];
        *reinterpret_cast<uint2*>(Qsu + row0 * QST + col) =
            make_uint2(f2tf(s[0]), f2tf(s[1]));
        *reinterpret_cast<uint2*>(Qsu + (row0 + 8) * QST + col) =
            make_uint2(f2tf(s[2]), f2tf(s[3]));
      }
    }
    __syncthreads();

    // ---- O += P · V  (warp: 32m x 32d)
#pragma unroll 4
    for (int k0 = 0; k0 < 128; k0 += 8) {
      uint32_t A[2][4];
#pragma unroll
      for (int mt = 0; mt < 2; mt++) {
        const uint32_t* ab = Qsu + (wm + mt * 16 + qr) * QST + k0 + qc;
        A[mt][0] = ab[0];
        A[mt][1] = ab[8 * QST];
        A[mt][2] = ab[4];
        A[mt][3] = ab[8 * QST + 4];
      }
#pragma unroll
      for (int nt = 0; nt < 4; nt++) {
        const int d = wn + nt * 8 + qr;
        uint32_t b0 = Vsu[(k0 + qc) * VST + d];
        uint32_t b1 = Vsu[(k0 + qc + 4) * VST + d];
        mma_tf32(O[0][nt], A[0], b0, b1);
        mma_tf32(O[1][nt], A[1], b0, b1);
      }
    }
  }

  // combine row sums across the 4 n-warps
  if (qc == 0) {
#pragma unroll
    for (int r = 0; r < 4; r++)
      l_sh[(wid >> 2) * 128 + wm + row_rel[r]] = L[r];
  }
  __syncthreads();
  float linv[4];
#pragma unroll
  for (int r = 0; r < 4; r++) {
    int row = wm + row_rel[r];
    linv[r] = 1.f / (l_sh[row] + l_sh[128 + row] + l_sh[256 + row] + l_sh[384 + row]);
  }

#pragma unroll
  for (int mt = 0; mt < 2; mt++) {
#pragma unroll
    for (int nt = 0; nt < 4; nt++) {
      const int row0 = wm + mt * 16 + qr;
      const int col = h * DIMD + wn + nt * 8 + 2 * qc;
      const float* o = O[mt][nt];
      float2 a = make_float2(o[0] * linv[mt * 2], o[1] * linv[mt * 2]);
      float2 b = make_float2(o[2] * linv[mt * 2 + 1], o[3] * linv[mt * 2 + 1]);
      *reinterpret_cast<float2*>(g_ctx + (size_t)(i0 + row0) * (HEADS * DIMD) + col) = a;
      *reinterpret_cast<float2*>(g_ctx + (size_t)(i0 + row0 + 8) * (HEADS * DIMD) + col) = b;
    }
  }
}

// ======================= kernel 3: out (tf32 tensor, split-K) ==================
__global__ void __launch_bounds__(256) out_tc_kernel(const float* __restrict__ last) {
  extern __shared__ float sm[];
  uint32_t* Xs = reinterpret_cast<uint32_t*>(sm);
  uint32_t* Bt = reinterpret_cast<uint32_t*>(sm + 128 * PST);

  const int m0 = blockIdx.x * 128;
  const int kc = blockIdx.y;
  const int tid = threadIdx.x;
  const int wid = tid >> 5;
  const int lane = tid & 31;
  const int qr = lane >> 2, qc = lane & 3;
  const int wm = (wid & 3) * 32;
  const int wn = (wid >> 2) * 64;

  float O[2][8][4];
#pragma unroll
  for (int mt = 0; mt < 2; mt++)
#pragma unroll
    for (int nt = 0; nt < 8; nt++)
#pragma unroll
      for (int e = 0; e < 4; e++) O[mt][nt][e] = 0.f;

  for (int ks = 0; ks < 2; ks++) {
    const int kb = kc * 256 + ks * 128;
    __syncthreads();
    for (int idx = tid; idx < 128 * 32; idx += 256) {
      int r = idx >> 5, c4 = (idx & 31) << 2;
      float4 t = *reinterpret_cast<const float4*>(
          g_ctx + (size_t)(m0 + r) * (HEADS * DIMD) + kb + c4);
      uint4 u = make_uint4(f2tf(t.x), f2tf(t.y), f2tf(t.z), f2tf(t.w));
      *reinterpret_cast<uint4*>(Xs + r * PST + c4) = u;
    }
    for (int idx = tid; idx < 128 * 32; idx += 256) {
      int e = idx & 127, k4 = (idx >> 7) << 2;
      uint4 u = make_uint4(f2tf(last[(size_t)(kb + k4 + 0) * DIMD + e]),
                           f2tf(last[(size_t)(kb + k4 + 1) * DIMD + e]),
                           f2tf(last[(size_t)(kb + k4 + 2) * DIMD + e]),
                           f2tf(last[(size_t)(kb + k4 + 3) * DIMD + e]));
      *reinterpret_cast<uint4*>(Bt + e * PST + k4) = u;
    }
    __syncthreads();

#pragma unroll 4
    for (int k0 = 0; k0 < 128; k0 += 8) {
      uint32_t Af[2][4];
#pragma unroll
      for (int mt = 0; mt < 2; mt++) {
        const uint32_t* ab = Xs + (wm + mt * 16 + qr) * PST + k0 + qc;
        Af[mt][0] = ab[0];
        Af[mt][1] = ab[8 * PST];
        Af[mt][2] = ab[4];
        Af[mt][3] = ab[8 * PST + 4];
      }
#pragma unroll
      for (int nt = 0; nt < 8; nt++) {
        const uint32_t* bb = Bt + (wn + nt * 8 + qr) * PST + k0 + qc;
        uint32_t b0 = bb[0], b1 = bb[4];
        mma_tf32(O[0][nt], Af[0], b0, b1);
        mma_tf32(O[1][nt], Af[1], b0, b1);
      }
    }
  }

  float* Pb = g_part + (size_t)kc * NSEQ * DIMD + (size_t)m0 * DIMD;
#pragma unroll
  for (int mt = 0; mt < 2; mt++) {
#pragma unroll
    for (int nt = 0; nt < 8; nt++) {
      const int row0 = wm + mt * 16 + qr;
      const int col = wn + nt * 8 + 2 * qc;
      const float* o = O[mt][nt];
      *reinterpret_cast<float2*>(Pb + (size_t)row0 * DIMD + col) = make_float2(o[0], o[1]);
      *reinterpret_cast<float2*>(Pb + (size_t)(row0 + 8) * DIMD + col) = make_float2(o[2], o[3]);
    }
  }
}

__global__ void __launch_bounds__(256) reduce_kernel(float* __restrict__ out) {
  int i = blockIdx.x * 256 + threadIdx.x;
  const float4* p = reinterpret_cast<const float4*>(g_part);
  float4 a = p[i];
#pragma unroll
  for (int kc = 1; kc < KSPLIT; kc++) {
    float4 b = p[(size_t)kc * (NSEQ * DIMD / 4) + i];
    a.x += b.x; a.y += b.y; a.z += b.z; a.w += b.w;
  }
  reinterpret_cast<float4*>(out)[i] = a;
}

// =====================================================================
extern "C" void kernel_launch(void* const* d_in, const int* in_sizes, int n_in,
                              void* d_out, int out_size) {
  int mi = -1;
  for (int i = 0; i < n_in; i++)
    if (in_sizes[i] == NSEQ * NSEQ) { mi = i; break; }
  if (mi < 0) mi = 3;

  const void* p[7];
  int np = 0;
  for (int i = 0; i < n_in && np < 7; i++) {
    if (i == mi) continue;
    p[np++] = d_in[i];
  }
  const float* q = (const float*)p[0];
  const float* k = (const float*)p[1];
  const float* v = (const float*)p[2];
  const float* Qw = (const float*)p[3];
  const float* Kw = (const float*)p[4];
  const float* Vw = (const float*)p[5];
  const float* last = (const float*)p[6];
  const int* mask = (const int*)d_in[mi];
  float* out = (float*)d_out;

  const int GEMM_SMEM = 2 * 128 * PST * 4;
  const int ATTN_SMEM = ATTN_SMEM_FLOATS * 4;  // 206,848 B

  cudaFuncSetAttribute(proj_tc_kernel, cudaFuncAttributeMaxDynamicSharedMemorySize, GEMM_SMEM);
  cudaFuncSetAttribute(out_tc_kernel, cudaFuncAttributeMaxDynamicSharedMemorySize, GEMM_SMEM);
  cudaFuncSetAttribute(attn_mma_kernel, cudaFuncAttributeMaxDynamicSharedMemorySize, ATTN_SMEM);

  maskbits_kernel<<<NSEQ * (NSEQ / 32) / 8, 256>>>(mask);
  proj_tc_kernel<<<dim3(NSEQ / 128, HEADS, 3), 256, GEMM_SMEM>>>(q, k, v, Qw, Kw, Vw);
  attn_mma_kernel<<<dim3(NSEQ / 128, HEADS), 512, ATTN_SMEM>>>();
  out_tc_kernel<<<dim3(NSEQ / 128, KSPLIT), 256, GEMM_SMEM>>>(last);
  reduce_kernel<<<NSEQ * DIMD / 4 / 256, 256>>>(out);
}

// round 6
// speedup vs baseline: 4.7985x; 1.1277x over previous
#include <cuda_runtime.h>
#include <cstdint>

#define HEADS 16
#define DIMD 128
#define NSEQ 2048
#define INV_SQRT_N 0.02209708691207961f /* 1/sqrt(2048) */
#define KSPLIT 8

// ---------------- scratch (static device globals; no allocations) ----------------
__device__ __align__(16) float g_qp[HEADS * NSEQ * DIMD];
__device__ __align__(16) float g_kp[HEADS * NSEQ * DIMD];
__device__ __align__(16) float g_vp[HEADS * NSEQ * DIMD];
__device__ __align__(16) float g_ctx[NSEQ * HEADS * DIMD];
__device__ __align__(16) float g_part[KSPLIT * NSEQ * DIMD];
__device__ __align__(16) unsigned g_mbits[NSEQ * (NSEQ / 32)];

// ---------------- helpers ----------------
__device__ __forceinline__ uint32_t f2tf(float x) {
  uint32_t r;
  asm("cvt.rna.tf32.f32 %0, %1;" : "=r"(r) : "f"(x));
  return r;
}
// pack two floats into f16x2: lo -> low half, hi -> high half
__device__ __forceinline__ uint32_t f2h2(float lo, float hi) {
  uint32_t r;
  asm("cvt.rn.f16x2.f32 %0, %1, %2;" : "=r"(r) : "f"(hi), "f"(lo));
  return r;
}

__device__ __forceinline__ void mma_tf32(float c[4], const uint32_t a[4],
                                         uint32_t b0, uint32_t b1) {
  asm volatile(
      "mma.sync.aligned.m16n8k8.row.col.f32.tf32.tf32.f32 "
      "{%0,%1,%2,%3}, {%4,%5,%6,%7}, {%8,%9}, {%0,%1,%2,%3};"
      : "+f"(c[0]), "+f"(c[1]), "+f"(c[2]), "+f"(c[3])
      : "r"(a[0]), "r"(a[1]), "r"(a[2]), "r"(a[3]), "r"(b0), "r"(b1));
}

__device__ __forceinline__ void mma_f16(float c[4], const uint32_t a[4],
                                        uint32_t b0, uint32_t b1) {
  asm volatile(
      "mma.sync.aligned.m16n8k16.row.col.f32.f16.f16.f32 "
      "{%0,%1,%2,%3}, {%4,%5,%6,%7}, {%8,%9}, {%0,%1,%2,%3};"
      : "+f"(c[0]), "+f"(c[1]), "+f"(c[2]), "+f"(c[3])
      : "r"(a[0]), "r"(a[1]), "r"(a[2]), "r"(a[3]), "r"(b0), "r"(b1));
}

// ======================= kernel 0: pack mask into bits =======================
__global__ void __launch_bounds__(256) maskbits_kernel(const int* __restrict__ mask) {
  int w = blockIdx.x * 8 + (threadIdx.x >> 5);
  int lane = threadIdx.x & 31;
  int m = mask[(size_t)w * 32 + lane];
  unsigned bits = __ballot_sync(0xffffffffu, m != 0);
  if (lane == 0) g_mbits[w] = bits;
}

// ======================= kernel 1: projections (tf32 tensor) ==================
#define PST 132
__global__ void __launch_bounds__(256) proj_tc_kernel(
    const float* __restrict__ q, const float* __restrict__ k,
    const float* __restrict__ v, const float* __restrict__ Qw,
    const float* __restrict__ Kw, const float* __restrict__ Vw) {
  extern __shared__ float sm[];
  uint32_t* Xs = reinterpret_cast<uint32_t*>(sm);              // [n=128][d=128] st 132
  uint32_t* Ws = reinterpret_cast<uint32_t*>(sm + 128 * PST);  // [e=128][d=128] st 132 (W^T)

  const int which = blockIdx.z;
  const float* A = (which == 0) ? q : (which == 1) ? k : v;
  const float* W = (which == 0) ? Qw : (which == 1) ? Kw : Vw;
  float* C = (which == 0) ? g_qp : (which == 1) ? g_kp : g_vp;
  const int h = blockIdx.y;
  const int n0 = blockIdx.x * 128;
  const int tid = threadIdx.x;
  const int wid = tid >> 5;
  const int lane = tid & 31;
  const int qr = lane >> 2, qc = lane & 3;
  const int wm = (wid & 3) * 32;
  const int wn = (wid >> 2) * 64;

  for (int idx = tid; idx < 128 * 32; idx += 256) {
    int r = idx >> 5, c4 = (idx & 31) << 2;
    float4 t = *reinterpret_cast<const float4*>(A + (size_t)(n0 + r) * DIMD + c4);
    uint4 u = make_uint4(f2tf(t.x), f2tf(t.y), f2tf(t.z), f2tf(t.w));
    *reinterpret_cast<uint4*>(Xs + r * PST + c4) = u;
  }
  const float* Wh = W + (size_t)h * DIMD * DIMD;
  for (int idx = tid; idx < 128 * 32; idx += 256) {
    int e = idx & 127, d4 = (idx >> 7) << 2;
    uint4 u = make_uint4(f2tf(Wh[(d4 + 0) * DIMD + e]), f2tf(Wh[(d4 + 1) * DIMD + e]),
                         f2tf(Wh[(d4 + 2) * DIMD + e]), f2tf(Wh[(d4 + 3) * DIMD + e]));
    *reinterpret_cast<uint4*>(Ws + e * PST + d4) = u;
  }
  __syncthreads();

  float O[2][8][4];
#pragma unroll
  for (int mt = 0; mt < 2; mt++)
#pragma unroll
    for (int nt = 0; nt < 8; nt++)
#pragma unroll
      for (int e = 0; e < 4; e++) O[mt][nt][e] = 0.f;

#pragma unroll 4
  for (int k0 = 0; k0 < 128; k0 += 8) {
    uint32_t Af[2][4];
#pragma unroll
    for (int mt = 0; mt < 2; mt++) {
      const uint32_t* ab = Xs + (wm + mt * 16 + qr) * PST + k0 + qc;
      Af[mt][0] = ab[0];
      Af[mt][1] = ab[8 * PST];
      Af[mt][2] = ab[4];
      Af[mt][3] = ab[8 * PST + 4];
    }
#pragma unroll
    for (int nt = 0; nt < 8; nt++) {
      const uint32_t* bb = Ws + (wn + nt * 8 + qr) * PST + k0 + qc;
      uint32_t b0 = bb[0], b1 = bb[4];
      mma_tf32(O[0][nt], Af[0], b0, b1);
      mma_tf32(O[1][nt], Af[1], b0, b1);
    }
  }

  float* Cb = C + ((size_t)h * NSEQ + n0) * DIMD;
#pragma unroll
  for (int mt = 0; mt < 2; mt++) {
#pragma unroll
    for (int nt = 0; nt < 8; nt++) {
      const int row0 = wm + mt * 16 + qr;
      const int col = wn + nt * 8 + 2 * qc;
      const float* o = O[mt][nt];
      *reinterpret_cast<float2*>(Cb + (size_t)row0 * DIMD + col) = make_float2(o[0], o[1]);
      *reinterpret_cast<float2*>(Cb + (size_t)(row0 + 8) * DIMD + col) = make_float2(o[2], o[3]);
    }
  }
}

// ======================= kernel 2: attention, f16 S-phase + tf32 PV =========
// Block: one head, 128 K-rows. 16 warps, 4m x 4n (32x32 warp tiles).
// smem (uint32/float units):
//   Ks2 [128][68]  f16x2  (K tile, 34,816 B)
//   Qs2 [128][68]  f16x2  (Q tile, 34,816 B)
//   P   [128][132] f32/tf32 (67,584 B)
//   V   [128][136] f32/tf32 (69,632 B)
//   l   [4][128]   f32     (2,048 B)
#define AT_QU 8704          /* uint32 offset of Qs2 */
#define AT_P 17408          /* float offset of P */
#define AT_V 34304          /* float offset of V */
#define AT_L 51712          /* float offset of l */
#define ATTN_SMEM_BYTES (52224 * 4)
#define VST 136

__global__ void __launch_bounds__(512) attn_mma_kernel() {
  extern __shared__ float sm[];
  uint32_t* Ks2 = reinterpret_cast<uint32_t*>(sm);
  uint32_t* Qs2 = reinterpret_cast<uint32_t*>(sm) + AT_QU;
  uint32_t* Psu = reinterpret_cast<uint32_t*>(sm + AT_P);
  uint32_t* Vsu = reinterpret_cast<uint32_t*>(sm + AT_V);
  float* l_sh = sm + AT_L;

  const int tid = threadIdx.x;
  const int wid = tid >> 5;
  const int lane = tid & 31;
  const int qr = lane >> 2;
  const int qc = lane & 3;
  const int wm = (wid & 3) * 32;
  const int wn = (wid >> 2) * 32;

  const int h = blockIdx.y;
  const int i0 = blockIdx.x * 128;

  const float* kp = g_kp + (size_t)h * NSEQ * DIMD;
  const float* qp = g_qp + (size_t)h * NSEQ * DIMD;
  const float* vp = g_vp + (size_t)h * NSEQ * DIMD;

  // K tile (persistent), f16
  for (int idx = tid; idx < 128 * 32; idx += 512) {
    int r = idx >> 5, c4 = (idx & 31) << 2;
    float4 t = *reinterpret_cast<const float4*>(kp + (size_t)(i0 + r) * DIMD + c4);
    *reinterpret_cast<uint2*>(Ks2 + r * 68 + ((idx & 31) << 1)) =
        make_uint2(f2h2(t.x, t.y), f2h2(t.z, t.w));
  }

  // prefetch Q tile 0 into regs
  float4 qpre[8];
#pragma unroll
  for (int p = 0; p < 8; p++) {
    int idx = tid + p * 512;
    int r = idx >> 5, c4 = (idx & 31) << 2;
    qpre[p] = *reinterpret_cast<const float4*>(qp + (size_t)r * DIMD + c4);
  }

  float O[2][4][4];
#pragma unroll
  for (int mt = 0; mt < 2; mt++)
#pragma unroll
    for (int nt = 0; nt < 4; nt++)
#pragma unroll
      for (int e = 0; e < 4; e++) O[mt][nt][e] = 0.f;
  float L[4] = {0.f, 0.f, 0.f, 0.f};

  const int row_rel[4] = {qr, qr + 8, qr + 16, qr + 24};

  for (int jt = 0; jt < NSEQ / 128; jt++) {
    const int j0 = jt * 128;
    __syncthreads();  // prev PV done reading P and V

    // store prefetched Q (f16); LDG+cvt+STS V (tf32)
#pragma unroll
    for (int p = 0; p < 8; p++) {
      int idx = tid + p * 512;
      int r = idx >> 5, c4 = (idx & 31) << 2;
      float4 t = qpre[p];
      *reinterpret_cast<uint2*>(Qs2 + r * 68 + ((idx & 31) << 1)) =
          make_uint2(f2h2(t.x, t.y), f2h2(t.z, t.w));
      float4 tv = *reinterpret_cast<const float4*>(vp + (size_t)(j0 + r) * DIMD + c4);
      *reinterpret_cast<uint4*>(Vsu + r * VST + c4) =
          make_uint4(f2tf(tv.x), f2tf(tv.y), f2tf(tv.z), f2tf(tv.w));
    }
    // prefetch next Q tile (overlaps S-phase)
    if (jt < NSEQ / 128 - 1) {
      const int jn = j0 + 128;
#pragma unroll
      for (int p = 0; p < 8; p++) {
        int idx = tid + p * 512;
        int r = idx >> 5, c4 = (idx & 31) << 2;
        qpre[p] = *reinterpret_cast<const float4*>(qp + (size_t)(jn + r) * DIMD + c4);
      }
    }
    __syncthreads();

    // ---- S = K · Q^T  (f16, k=16 per MMA; warp: 32m x 32n)
    float S[2][4][4];
#pragma unroll
    for (int mt = 0; mt < 2; mt++)
#pragma unroll
      for (int nt = 0; nt < 4; nt++)
#pragma unroll
        for (int e = 0; e < 4; e++) S[mt][nt][e] = 0.f;

#pragma unroll
    for (int ks = 0; ks < 8; ks++) {
      const int k8 = ks * 8;
      uint32_t A[2][4];
#pragma unroll
      for (int mt = 0; mt < 2; mt++) {
        const uint32_t* ab = Ks2 + (wm + mt * 16 + qr) * 68 + k8 + qc;
        A[mt][0] = ab[0];
        A[mt][1] = ab[8 * 68];
        A[mt][2] = ab[4];
        A[mt][3] = ab[8 * 68 + 4];
      }
#pragma unroll
      for (int nt = 0; nt < 4; nt++) {
        const uint32_t* bb = Qs2 + (wn + nt * 8 + qr) * 68 + k8 + qc;
        uint32_t b0 = bb[0], b1 = bb[4];
        mma_f16(S[0][nt], A[0], b0, b1);
        mma_f16(S[1][nt], A[1], b0, b1);
      }
    }

    // ---- masked exp (no max)
    unsigned mw[4];
#pragma unroll
    for (int r = 0; r < 4; r++)
      mw[r] = g_mbits[(size_t)(i0 + wm + row_rel[r]) * (NSEQ / 32) + ((j0 + wn) >> 5)];

    float lacc[4] = {0.f, 0.f, 0.f, 0.f};
#pragma unroll
    for (int mt = 0; mt < 2; mt++) {
#pragma unroll
      for (int nt = 0; nt < 4; nt++) {
        const int b0 = nt * 8 + 2 * qc;
        const unsigned w0 = mw[mt * 2], w1 = mw[mt * 2 + 1];
        float* s = S[mt][nt];
        float p0 = ((w0 >> b0) & 1u) ? __expf(s[0] * INV_SQRT_N) : 0.f;
        float p1 = ((w0 >> (b0 + 1)) & 1u) ? __expf(s[1] * INV_SQRT_N) : 0.f;
        float p2 = ((w1 >> b0) & 1u) ? __expf(s[2] * INV_SQRT_N) : 0.f;
        float p3 = ((w1 >> (b0 + 1)) & 1u) ? __expf(s[3] * INV_SQRT_N) : 0.f;
        s[0] = p0; s[1] = p1; s[2] = p2; s[3] = p3;
        lacc[mt * 2] += p0 + p1;
        lacc[mt * 2 + 1] += p2 + p3;
      }
    }
#pragma unroll
    for (int r = 0; r < 4; r++) {
      float v = lacc[r];
      v += __shfl_xor_sync(0xffffffffu, v, 1);
      v += __shfl_xor_sync(0xffffffffu, v, 2);
      L[r] += v;
    }

    // P has its own buffer: no sync needed before writing it
#pragma unroll
    for (int mt = 0; mt < 2; mt++) {
#pragma unroll
      for (int nt = 0; nt < 4; nt++) {
        const int row0 = wm + mt * 16 + qr;
        const int col = wn + nt * 8 + 2 * qc;
        const float* s = S[mt][nt];
        *reinterpret_cast<uint2*>(Psu + row0 * PST + col) =
            make_uint2(f2tf(s[0]), f2tf(s[1]));
        *reinterpret_cast<uint2*>(Psu + (row0 + 8) * PST + col) =
            make_uint2(f2tf(s[2]), f2tf(s[3]));
      }
    }
    __syncthreads();

    // ---- O += P · V  (tf32; warp: 32m x 32d)
#pragma unroll 4
    for (int k0 = 0; k0 < 128; k0 += 8) {
      uint32_t A[2][4];
#pragma unroll
      for (int mt = 0; mt < 2; mt++) {
        const uint32_t* ab = Psu + (wm + mt * 16 + qr) * PST + k0 + qc;
        A[mt][0] = ab[0];
        A[mt][1] = ab[8 * PST];
        A[mt][2] = ab[4];
        A[mt][3] = ab[8 * PST + 4];
      }
#pragma unroll
      for (int nt = 0; nt < 4; nt++) {
        const int d = wn + nt * 8 + qr;
        uint32_t b0 = Vsu[(k0 + qc) * VST + d];
        uint32_t b1 = Vsu[(k0 + qc + 4) * VST + d];
        mma_tf32(O[0][nt], A[0], b0, b1);
        mma_tf32(O[1][nt], A[1], b0, b1);
      }
    }
  }

  // combine row sums across the 4 n-warps
  if (qc == 0) {
#pragma unroll
    for (int r = 0; r < 4; r++)
      l_sh[(wid >> 2) * 128 + wm + row_rel[r]] = L[r];
  }
  __syncthreads();
  float linv[4];
#pragma unroll
  for (int r = 0; r < 4; r++) {
    int row = wm + row_rel[r];
    linv[r] = 1.f / (l_sh[row] + l_sh[128 + row] + l_sh[256 + row] + l_sh[384 + row]);
  }

#pragma unroll
  for (int mt = 0; mt < 2; mt++) {
#pragma unroll
    for (int nt = 0; nt < 4; nt++) {
      const int row0 = wm + mt * 16 + qr;
      const int col = h * DIMD + wn + nt * 8 + 2 * qc;
      const float* o = O[mt][nt];
      float2 a = make_float2(o[0] * linv[mt * 2], o[1] * linv[mt * 2]);
      float2 b = make_float2(o[2] * linv[mt * 2 + 1], o[3] * linv[mt * 2 + 1]);
      *reinterpret_cast<float2*>(g_ctx + (size_t)(i0 + row0) * (HEADS * DIMD) + col) = a;
      *reinterpret_cast<float2*>(g_ctx + (size_t)(i0 + row0 + 8) * (HEADS * DIMD) + col) = b;
    }
  }
}

// ======================= kernel 3: out (tf32 tensor, split-K) ==================
__global__ void __launch_bounds__(256) out_tc_kernel(const float* __restrict__ last) {
  extern __shared__ float sm[];
  uint32_t* Xs = reinterpret_cast<uint32_t*>(sm);
  uint32_t* Bt = reinterpret_cast<uint32_t*>(sm + 128 * PST);

  const int m0 = blockIdx.x * 128;
  const int kc = blockIdx.y;
  const int tid = threadIdx.x;
  const int wid = tid >> 5;
  const int lane = tid & 31;
  const int qr = lane >> 2, qc = lane & 3;
  const int wm = (wid & 3) * 32;
  const int wn = (wid >> 2) * 64;

  float O[2][8][4];
#pragma unroll
  for (int mt = 0; mt < 2; mt++)
#pragma unroll
    for (int nt = 0; nt < 8; nt++)
#pragma unroll
      for (int e = 0; e < 4; e++) O[mt][nt][e] = 0.f;

  for (int ks = 0; ks < 2; ks++) {
    const int kb = kc * 256 + ks * 128;
    __syncthreads();
    for (int idx = tid; idx < 128 * 32; idx += 256) {
      int r = idx >> 5, c4 = (idx & 31) << 2;
      float4 t = *reinterpret_cast<const float4*>(
          g_ctx + (size_t)(m0 + r) * (HEADS * DIMD) + kb + c4);
      uint4 u = make_uint4(f2tf(t.x), f2tf(t.y), f2tf(t.z), f2tf(t.w));
      *reinterpret_cast<uint4*>(Xs + r * PST + c4) = u;
    }
    for (int idx = tid; idx < 128 * 32; idx += 256) {
      int e = idx & 127, k4 = (idx >> 7) << 2;
      uint4 u = make_uint4(f2tf(last[(size_t)(kb + k4 + 0) * DIMD + e]),
                           f2tf(last[(size_t)(kb + k4 + 1) * DIMD + e]),
                           f2tf(last[(size_t)(kb + k4 + 2) * DIMD + e]),
                           f2tf(last[(size_t)(kb + k4 + 3) * DIMD + e]));
      *reinterpret_cast<uint4*>(Bt + e * PST + k4) = u;
    }
    __syncthreads();

#pragma unroll 4
    for (int k0 = 0; k0 < 128; k0 += 8) {
      uint32_t Af[2][4];
#pragma unroll
      for (int mt = 0; mt < 2; mt++) {
        const uint32_t* ab = Xs + (wm + mt * 16 + qr) * PST + k0 + qc;
        Af[mt][0] = ab[0];
        Af[mt][1] = ab[8 * PST];
        Af[mt][2] = ab[4];
        Af[mt][3] = ab[8 * PST + 4];
      }
#pragma unroll
      for (int nt = 0; nt < 8; nt++) {
        const uint32_t* bb = Bt + (wn + nt * 8 + qr) * PST + k0 + qc;
        uint32_t b0 = bb[0], b1 = bb[4];
        mma_tf32(O[0][nt], Af[0], b0, b1);
        mma_tf32(O[1][nt], Af[1], b0, b1);
      }
    }
  }

  float* Pb = g_part + (size_t)kc * NSEQ * DIMD + (size_t)m0 * DIMD;
#pragma unroll
  for (int mt = 0; mt < 2; mt++) {
#pragma unroll
    for (int nt = 0; nt < 8; nt++) {
      const int row0 = wm + mt * 16 + qr;
      const int col = wn + nt * 8 + 2 * qc;
      const float* o = O[mt][nt];
      *reinterpret_cast<float2*>(Pb + (size_t)row0 * DIMD + col) = make_float2(o[0], o[1]);
      *reinterpret_cast<float2*>(Pb + (size_t)(row0 + 8) * DIMD + col) = make_float2(o[2], o[3]);
    }
  }
}

__global__ void __launch_bounds__(256) reduce_kernel(float* __restrict__ out) {
  int i = blockIdx.x * 256 + threadIdx.x;
  const float4* p = reinterpret_cast<const float4*>(g_part);
  float4 a = p[i];
#pragma unroll
  for (int kc = 1; kc < KSPLIT; kc++) {
    float4 b = p[(size_t)kc * (NSEQ * DIMD / 4) + i];
    a.x += b.x; a.y += b.y; a.z += b.z; a.w += b.w;
  }
  reinterpret_cast<float4*>(out)[i] = a;
}

// =====================================================================
extern "C" void kernel_launch(void* const* d_in, const int* in_sizes, int n_in,
                              void* d_out, int out_size) {
  int mi = -1;
  for (int i = 0; i < n_in; i++)
    if (in_sizes[i] == NSEQ * NSEQ) { mi = i; break; }
  if (mi < 0) mi = 3;

  const void* p[7];
  int np = 0;
  for (int i = 0; i < n_in && np < 7; i++) {
    if (i == mi) continue;
    p[np++] = d_in[i];
  }
  const float* q = (const float*)p[0];
  const float* k = (const float*)p[1];
  const float* v = (const float*)p[2];
  const float* Qw = (const float*)p[3];
  const float* Kw = (const float*)p[4];
  const float* Vw = (const float*)p[5];
  const float* last = (const float*)p[6];
  const int* mask = (const int*)d_in[mi];
  float* out = (float*)d_out;

  const int GEMM_SMEM = 2 * 128 * PST * 4;

  cudaFuncSetAttribute(proj_tc_kernel, cudaFuncAttributeMaxDynamicSharedMemorySize, GEMM_SMEM);
  cudaFuncSetAttribute(out_tc_kernel, cudaFuncAttributeMaxDynamicSharedMemorySize, GEMM_SMEM);
  cudaFuncSetAttribute(attn_mma_kernel, cudaFuncAttributeMaxDynamicSharedMemorySize,
                       ATTN_SMEM_BYTES);

  maskbits_kernel<<<NSEQ * (NSEQ / 32) / 8, 256>>>(mask);
  proj_tc_kernel<<<dim3(NSEQ / 128, HEADS, 3), 256, GEMM_SMEM>>>(q, k, v, Qw, Kw, Vw);
  attn_mma_kernel<<<dim3(NSEQ / 128, HEADS), 512, ATTN_SMEM_BYTES>>>();
  out_tc_kernel<<<dim3(NSEQ / 128, KSPLIT), 256, GEMM_SMEM>>>(last);
  reduce_kernel<<<NSEQ * DIMD / 4 / 256, 256>>>(out);
}

// round 7
// speedup vs baseline: 6.1235x; 1.2761x over previous
#include <cuda_runtime.h>
#include <cstdint>

#define HEADS 16
#define DIMD 128
#define NSEQ 2048
#define INV_SQRT_N 0.02209708691207961f /* 1/sqrt(2048) */
#define KSPLIT 8

// ---------------- scratch (static device globals; no allocations) ----------------
__device__ __align__(16) uint32_t g_qp2[HEADS * NSEQ * 64];  // f16x2 packed
__device__ __align__(16) uint32_t g_kp2[HEADS * NSEQ * 64];  // f16x2 packed
__device__ __align__(16) float g_vp[HEADS * NSEQ * DIMD];
__device__ __align__(16) float g_ctx[NSEQ * HEADS * DIMD];
__device__ __align__(16) float g_part[KSPLIT * NSEQ * DIMD];
__device__ __align__(16) unsigned g_mbits[NSEQ * (NSEQ / 32)];

// ---------------- helpers ----------------
__device__ __forceinline__ uint32_t f2tf(float x) {
  uint32_t r;
  asm("cvt.rna.tf32.f32 %0, %1;" : "=r"(r) : "f"(x));
  return r;
}
// pack two floats into f16x2: lo -> low half, hi -> high half
__device__ __forceinline__ uint32_t f2h2(float lo, float hi) {
  uint32_t r;
  asm("cvt.rn.f16x2.f32 %0, %1, %2;" : "=r"(r) : "f"(hi), "f"(lo));
  return r;
}
__device__ __forceinline__ uint32_t smem_u32(const void* p) {
  uint32_t a;
  asm("{ .reg .u64 t; cvta.to.shared.u64 t, %1; cvt.u32.u64 %0, t; }" : "=r"(a) : "l"(p));
  return a;
}

__device__ __forceinline__ void mma_tf32(float c[4], const uint32_t a[4],
                                         uint32_t b0, uint32_t b1) {
  asm volatile(
      "mma.sync.aligned.m16n8k8.row.col.f32.tf32.tf32.f32 "
      "{%0,%1,%2,%3}, {%4,%5,%6,%7}, {%8,%9}, {%0,%1,%2,%3};"
      : "+f"(c[0]), "+f"(c[1]), "+f"(c[2]), "+f"(c[3])
      : "r"(a[0]), "r"(a[1]), "r"(a[2]), "r"(a[3]), "r"(b0), "r"(b1));
}

__device__ __forceinline__ void mma_f16(float c[4], const uint32_t a[4],
                                        uint32_t b0, uint32_t b1) {
  asm volatile(
      "mma.sync.aligned.m16n8k16.row.col.f32.f16.f16.f32 "
      "{%0,%1,%2,%3}, {%4,%5,%6,%7}, {%8,%9}, {%0,%1,%2,%3};"
      : "+f"(c[0]), "+f"(c[1]), "+f"(c[2]), "+f"(c[3])
      : "r"(a[0]), "r"(a[1]), "r"(a[2]), "r"(a[3]), "r"(b0), "r"(b1));
}

__device__ __forceinline__ void ldmatrix_x4_trans(uint32_t& r0, uint32_t& r1,
                                                  uint32_t& r2, uint32_t& r3,
                                                  uint32_t addr) {
  asm volatile(
      "ldmatrix.sync.aligned.m8n8.x4.trans.shared.b16 {%0,%1,%2,%3}, [%4];"
      : "=r"(r0), "=r"(r1), "=r"(r2), "=r"(r3)
      : "r"(addr));
}

// ======================= kernel 0: pack mask into bits =======================
__global__ void __launch_bounds__(256) maskbits_kernel(const int* __restrict__ mask) {
  int w = blockIdx.x * 8 + (threadIdx.x >> 5);
  int lane = threadIdx.x & 31;
  int m = mask[(size_t)w * 32 + lane];
  unsigned bits = __ballot_sync(0xffffffffu, m != 0);
  if (lane == 0) g_mbits[w] = bits;
}

// ======================= kernel 1: projections (tf32 tensor) ==================
// which 0/1 (q,k): writes f16x2; which 2 (v): writes f32.
#define PST 132
__global__ void __launch_bounds__(256) proj_tc_kernel(
    const float* __restrict__ q, const float* __restrict__ k,
    const float* __restrict__ v, const float* __restrict__ Qw,
    const float* __restrict__ Kw, const float* __restrict__ Vw) {
  extern __shared__ float sm[];
  uint32_t* Xs = reinterpret_cast<uint32_t*>(sm);
  uint32_t* Ws = reinterpret_cast<uint32_t*>(sm + 128 * PST);

  const int which = blockIdx.z;
  const float* A = (which == 0) ? q : (which == 1) ? k : v;
  const float* W = (which == 0) ? Qw : (which == 1) ? Kw : Vw;
  const int h = blockIdx.y;
  const int n0 = blockIdx.x * 128;
  const int tid = threadIdx.x;
  const int wid = tid >> 5;
  const int lane = tid & 31;
  const int qr = lane >> 2, qc = lane & 3;
  const int wm = (wid & 3) * 32;
  const int wn = (wid >> 2) * 64;

  for (int idx = tid; idx < 128 * 32; idx += 256) {
    int r = idx >> 5, c4 = (idx & 31) << 2;
    float4 t = *reinterpret_cast<const float4*>(A + (size_t)(n0 + r) * DIMD + c4);
    uint4 u = make_uint4(f2tf(t.x), f2tf(t.y), f2tf(t.z), f2tf(t.w));
    *reinterpret_cast<uint4*>(Xs + r * PST + c4) = u;
  }
  const float* Wh = W + (size_t)h * DIMD * DIMD;
  for (int idx = tid; idx < 128 * 32; idx += 256) {
    int e = idx & 127, d4 = (idx >> 7) << 2;
    uint4 u = make_uint4(f2tf(Wh[(d4 + 0) * DIMD + e]), f2tf(Wh[(d4 + 1) * DIMD + e]),
                         f2tf(Wh[(d4 + 2) * DIMD + e]), f2tf(Wh[(d4 + 3) * DIMD + e]));
    *reinterpret_cast<uint4*>(Ws + e * PST + d4) = u;
  }
  __syncthreads();

  float O[2][8][4];
#pragma unroll
  for (int mt = 0; mt < 2; mt++)
#pragma unroll
    for (int nt = 0; nt < 8; nt++)
#pragma unroll
      for (int e = 0; e < 4; e++) O[mt][nt][e] = 0.f;

#pragma unroll 4
  for (int k0 = 0; k0 < 128; k0 += 8) {
    uint32_t Af[2][4];
#pragma unroll
    for (int mt = 0; mt < 2; mt++) {
      const uint32_t* ab = Xs + (wm + mt * 16 + qr) * PST + k0 + qc;
      Af[mt][0] = ab[0];
      Af[mt][1] = ab[8 * PST];
      Af[mt][2] = ab[4];
      Af[mt][3] = ab[8 * PST + 4];
    }
#pragma unroll
    for (int nt = 0; nt < 8; nt++) {
      const uint32_t* bb = Ws + (wn + nt * 8 + qr) * PST + k0 + qc;
      uint32_t b0 = bb[0], b1 = bb[4];
      mma_tf32(O[0][nt], Af[0], b0, b1);
      mma_tf32(O[1][nt], Af[1], b0, b1);
    }
  }

  if (which < 2) {
    uint32_t* Cb2 = (which == 0 ? g_qp2 : g_kp2) + ((size_t)h * NSEQ + n0) * 64;
#pragma unroll
    for (int mt = 0; mt < 2; mt++) {
#pragma unroll
      for (int nt = 0; nt < 8; nt++) {
        const int row0 = wm + mt * 16 + qr;
        const int cu = (wn + nt * 8) / 2 + qc;  // col/2
        const float* o = O[mt][nt];
        Cb2[(size_t)row0 * 64 + cu] = f2h2(o[0], o[1]);
        Cb2[(size_t)(row0 + 8) * 64 + cu] = f2h2(o[2], o[3]);
      }
    }
  } else {
    float* Cb = g_vp + ((size_t)h * NSEQ + n0) * DIMD;
#pragma unroll
    for (int mt = 0; mt < 2; mt++) {
#pragma unroll
      for (int nt = 0; nt < 8; nt++) {
        const int row0 = wm + mt * 16 + qr;
        const int col = wn + nt * 8 + 2 * qc;
        const float* o = O[mt][nt];
        *reinterpret_cast<float2*>(Cb + (size_t)row0 * DIMD + col) = make_float2(o[0], o[1]);
        *reinterpret_cast<float2*>(Cb + (size_t)(row0 + 8) * DIMD + col) = make_float2(o[2], o[3]);
      }
    }
  }
}

// ======================= kernel 2: attention, all-f16 MMA =====================
// 16 warps, 4m x 4n (32x32 warp tiles). K/Q/P/V all f16 in smem (stride 68 u32).
// PV B-fragments via ldmatrix.x4.trans from naturally-stored V.
#define ATW 68
#define AT_K 0
#define AT_Q 8704
#define AT_PP 17408
#define AT_V 26112
#define AT_L 34816
#define ATTN_SMEM_BYTES ((34816 + 512) * 4)

__global__ void __launch_bounds__(512) attn_mma_kernel() {
  extern __shared__ uint32_t smu[];
  uint32_t* Ks2 = smu + AT_K;
  uint32_t* Qs2 = smu + AT_Q;
  uint32_t* Ps2 = smu + AT_PP;
  uint32_t* Vs2 = smu + AT_V;
  float* l_sh = reinterpret_cast<float*>(smu + AT_L);

  const int tid = threadIdx.x;
  const int wid = tid >> 5;
  const int lane = tid & 31;
  const int qr = lane >> 2;
  const int qc = lane & 3;
  const int wm = (wid & 3) * 32;
  const int wn = (wid >> 2) * 32;

  const int h = blockIdx.y;
  const int i0 = blockIdx.x * 128;

  const uint32_t* kp2 = g_kp2 + (size_t)h * NSEQ * 64;
  const uint32_t* qp2 = g_qp2 + (size_t)h * NSEQ * 64;
  const float* vp = g_vp + (size_t)h * NSEQ * DIMD;

  // K tile (persistent), f16 direct copy: 4 x uint4 per thread
#pragma unroll
  for (int p = 0; p < 4; p++) {
    int idx = tid + p * 512;
    int r = idx >> 4, c4 = (idx & 15) << 2;
    uint4 t = *reinterpret_cast<const uint4*>(kp2 + (size_t)(i0 + r) * 64 + c4);
    *reinterpret_cast<uint4*>(Ks2 + r * ATW + c4) = t;
  }

  // prefetch Q tile 0 into regs (4 x uint4)
  uint4 qpre[4];
#pragma unroll
  for (int p = 0; p < 4; p++) {
    int idx = tid + p * 512;
    int r = idx >> 4, c4 = (idx & 15) << 2;
    qpre[p] = *reinterpret_cast<const uint4*>(qp2 + (size_t)r * 64 + c4);
  }

  // ldmatrix lane-address components for V B-fragments
  const int lg = lane >> 3;                      // 0..3
  const int vrow0 = (lane & 7) + ((lg & 1) << 3);  // k-row within 16
  const int vn0 = (wn >> 1) + ((lg >> 1) << 2);    // u32 col offset
  const uint32_t vbase = smem_u32(Vs2);

  float O[2][4][4];
#pragma unroll
  for (int mt = 0; mt < 2; mt++)
#pragma unroll
    for (int nt = 0; nt < 4; nt++)
#pragma unroll
      for (int e = 0; e < 4; e++) O[mt][nt][e] = 0.f;
  float L[4] = {0.f, 0.f, 0.f, 0.f};

  const int row_rel[4] = {qr, qr + 8, qr + 16, qr + 24};

  for (int jt = 0; jt < NSEQ / 128; jt++) {
    const int j0 = jt * 128;
    __syncthreads();  // prev PV done reading Ps2/Vs2

    // store prefetched Q (f16 direct)
#pragma unroll
    for (int p = 0; p < 4; p++) {
      int idx = tid + p * 512;
      int r = idx >> 4, c4 = (idx & 15) << 2;
      *reinterpret_cast<uint4*>(Qs2 + r * ATW + c4) = qpre[p];
    }
    // V: LDG f32, cvt, natural f16 [j][d] store
#pragma unroll
    for (int p = 0; p < 8; p++) {
      int idx = tid + p * 512;
      int r = idx >> 5, c4 = (idx & 31) << 2;
      float4 tv = *reinterpret_cast<const float4*>(vp + (size_t)(j0 + r) * DIMD + c4);
      *reinterpret_cast<uint2*>(Vs2 + r * ATW + ((idx & 31) << 1)) =
          make_uint2(f2h2(tv.x, tv.y), f2h2(tv.z, tv.w));
    }
    // prefetch next Q tile
    if (jt < NSEQ / 128 - 1) {
      const int jn = j0 + 128;
#pragma unroll
      for (int p = 0; p < 4; p++) {
        int idx = tid + p * 512;
        int r = idx >> 4, c4 = (idx & 15) << 2;
        qpre[p] = *reinterpret_cast<const uint4*>(qp2 + (size_t)(jn + r) * 64 + c4);
      }
    }
    __syncthreads();

    // ---- S = K · Q^T  (f16 k16; warp: 32m x 32n)
    float S[2][4][4];
#pragma unroll
    for (int mt = 0; mt < 2; mt++)
#pragma unroll
      for (int nt = 0; nt < 4; nt++)
#pragma unroll
        for (int e = 0; e < 4; e++) S[mt][nt][e] = 0.f;

#pragma unroll
    for (int ks = 0; ks < 8; ks++) {
      const int k8 = ks * 8;
      uint32_t A[2][4];
#pragma unroll
      for (int mt = 0; mt < 2; mt++) {
        const uint32_t* ab = Ks2 + (wm + mt * 16 + qr) * ATW + k8 + qc;
        A[mt][0] = ab[0];
        A[mt][1] = ab[8 * ATW];
        A[mt][2] = ab[4];
        A[mt][3] = ab[8 * ATW + 4];
      }
#pragma unroll
      for (int nt = 0; nt < 4; nt++) {
        const uint32_t* bb = Qs2 + (wn + nt * 8 + qr) * ATW + k8 + qc;
        uint32_t b0 = bb[0], b1 = bb[4];
        mma_f16(S[0][nt], A[0], b0, b1);
        mma_f16(S[1][nt], A[1], b0, b1);
      }
    }

    // ---- masked exp (no max)
    unsigned mw[4];
#pragma unroll
    for (int r = 0; r < 4; r++)
      mw[r] = g_mbits[(size_t)(i0 + wm + row_rel[r]) * (NSEQ / 32) + ((j0 + wn) >> 5)];

    float lacc[4] = {0.f, 0.f, 0.f, 0.f};
#pragma unroll
    for (int mt = 0; mt < 2; mt++) {
#pragma unroll
      for (int nt = 0; nt < 4; nt++) {
        const int b0 = nt * 8 + 2 * qc;
        const unsigned w0 = mw[mt * 2], w1 = mw[mt * 2 + 1];
        float* s = S[mt][nt];
        float p0 = ((w0 >> b0) & 1u) ? __expf(s[0] * INV_SQRT_N) : 0.f;
        float p1 = ((w0 >> (b0 + 1)) & 1u) ? __expf(s[1] * INV_SQRT_N) : 0.f;
        float p2 = ((w1 >> b0) & 1u) ? __expf(s[2] * INV_SQRT_N) : 0.f;
        float p3 = ((w1 >> (b0 + 1)) & 1u) ? __expf(s[3] * INV_SQRT_N) : 0.f;
        s[0] = p0; s[1] = p1; s[2] = p2; s[3] = p3;
        lacc[mt * 2] += p0 + p1;
        lacc[mt * 2 + 1] += p2 + p3;
      }
    }
#pragma unroll
    for (int r = 0; r < 4; r++) {
      float v = lacc[r];
      v += __shfl_xor_sync(0xffffffffu, v, 1);
      v += __shfl_xor_sync(0xffffffffu, v, 2);
      L[r] += v;
    }

    // ---- P -> smem as f16x2 (own buffer; fragment pairs are adjacent cols)
#pragma unroll
    for (int mt = 0; mt < 2; mt++) {
#pragma unroll
      for (int nt = 0; nt < 4; nt++) {
        const int row0 = wm + mt * 16 + qr;
        const int cu = (wn >> 1) + nt * 4 + qc;
        const float* s = S[mt][nt];
        Ps2[row0 * ATW + cu] = f2h2(s[0], s[1]);
        Ps2[(row0 + 8) * ATW + cu] = f2h2(s[2], s[3]);
      }
    }
    __syncthreads();

    // ---- O += P · V  (f16 k16; V B-frags via ldmatrix.x4.trans)
    uint32_t vaddr0 = vbase + (uint32_t)(vrow0 * ATW + vn0) * 4u;
    uint32_t vaddr1 = vaddr0 + 32u;  // +8 u32 cols
#pragma unroll
    for (int ks = 0; ks < 8; ks++) {
      const int k8 = ks * 8;
      uint32_t A[2][4];
#pragma unroll
      for (int mt = 0; mt < 2; mt++) {
        const uint32_t* ab = Ps2 + (wm + mt * 16 + qr) * ATW + k8 + qc;
        A[mt][0] = ab[0];
        A[mt][1] = ab[8 * ATW];
        A[mt][2] = ab[4];
        A[mt][3] = ab[8 * ATW + 4];
      }
      uint32_t b0, b1, b2, b3;
      ldmatrix_x4_trans(b0, b1, b2, b3, vaddr0);
      mma_f16(O[0][0], A[0], b0, b1);
      mma_f16(O[1][0], A[1], b0, b1);
      mma_f16(O[0][1], A[0], b2, b3);
      mma_f16(O[1][1], A[1], b2, b3);
      ldmatrix_x4_trans(b0, b1, b2, b3, vaddr1);
      mma_f16(O[0][2], A[0], b0, b1);
      mma_f16(O[1][2], A[1], b0, b1);
      mma_f16(O[0][3], A[0], b2, b3);
      mma_f16(O[1][3], A[1], b2, b3);
      vaddr0 += 16u * ATW * 4u;
      vaddr1 += 16u * ATW * 4u;
    }
  }

  // combine row sums across the 4 n-warps
  if (qc == 0) {
#pragma unroll
    for (int r = 0; r < 4; r++)
      l_sh[(wid >> 2) * 128 + wm + row_rel[r]] = L[r];
  }
  __syncthreads();
  float linv[4];
#pragma unroll
  for (int r = 0; r < 4; r++) {
    int row = wm + row_rel[r];
    linv[r] = 1.f / (l_sh[row] + l_sh[128 + row] + l_sh[256 + row] + l_sh[384 + row]);
  }

#pragma unroll
  for (int mt = 0; mt < 2; mt++) {
#pragma unroll
    for (int nt = 0; nt < 4; nt++) {
      const int row0 = wm + mt * 16 + qr;
      const int col = h * DIMD + wn + nt * 8 + 2 * qc;
      const float* o = O[mt][nt];
      float2 a = make_float2(o[0] * linv[mt * 2], o[1] * linv[mt * 2]);
      float2 b = make_float2(o[2] * linv[mt * 2 + 1], o[3] * linv[mt * 2 + 1]);
      *reinterpret_cast<float2*>(g_ctx + (size_t)(i0 + row0) * (HEADS * DIMD) + col) = a;
      *reinterpret_cast<float2*>(g_ctx + (size_t)(i0 + row0 + 8) * (HEADS * DIMD) + col) = b;
    }
  }
}

// ======================= kernel 3: out (tf32 tensor, split-K) ==================
__global__ void __launch_bounds__(256) out_tc_kernel(const float* __restrict__ last) {
  extern __shared__ float sm[];
  uint32_t* Xs = reinterpret_cast<uint32_t*>(sm);
  uint32_t* Bt = reinterpret_cast<uint32_t*>(sm + 128 * PST);

  const int m0 = blockIdx.x * 128;
  const int kc = blockIdx.y;
  const int tid = threadIdx.x;
  const int wid = tid >> 5;
  const int lane = tid & 31;
  const int qr = lane >> 2, qc = lane & 3;
  const int wm = (wid & 3) * 32;
  const int wn = (wid >> 2) * 64;

  float O[2][8][4];
#pragma unroll
  for (int mt = 0; mt < 2; mt++)
#pragma unroll
    for (int nt = 0; nt < 8; nt++)
#pragma unroll
      for (int e = 0; e < 4; e++) O[mt][nt][e] = 0.f;

  for (int ks = 0; ks < 2; ks++) {
    const int kb = kc * 256 + ks * 128;
    __syncthreads();
    for (int idx = tid; idx < 128 * 32; idx += 256) {
      int r = idx >> 5, c4 = (idx & 31) << 2;
      float4 t = *reinterpret_cast<const float4*>(
          g_ctx + (size_t)(m0 + r) * (HEADS * DIMD) + kb + c4);
      uint4 u = make_uint4(f2tf(t.x), f2tf(t.y), f2tf(t.z), f2tf(t.w));
      *reinterpret_cast<uint4*>(Xs + r * PST + c4) = u;
    }
    for (int idx = tid; idx < 128 * 32; idx += 256) {
      int e = idx & 127, k4 = (idx >> 7) << 2;
      uint4 u = make_uint4(f2tf(last[(size_t)(kb + k4 + 0) * DIMD + e]),
                           f2tf(last[(size_t)(kb + k4 + 1) * DIMD + e]),
                           f2tf(last[(size_t)(kb + k4 + 2) * DIMD + e]),
                           f2tf(last[(size_t)(kb + k4 + 3) * DIMD + e]));
      *reinterpret_cast<uint4*>(Bt + e * PST + k4) = u;
    }
    __syncthreads();

#pragma unroll 4
    for (int k0 = 0; k0 < 128; k0 += 8) {
      uint32_t Af[2][4];
#pragma unroll
      for (int mt = 0; mt < 2; mt++) {
        const uint32_t* ab = Xs + (wm + mt * 16 + qr) * PST + k0 + qc;
        Af[mt][0] = ab[0];
        Af[mt][1] = ab[8 * PST];
        Af[mt][2] = ab[4];
        Af[mt][3] = ab[8 * PST + 4];
      }
#pragma unroll
      for (int nt = 0; nt < 8; nt++) {
        const uint32_t* bb = Bt + (wn + nt * 8 + qr) * PST + k0 + qc;
        uint32_t b0 = bb[0], b1 = bb[4];
        mma_tf32(O[0][nt], Af[0], b0, b1);
        mma_tf32(O[1][nt], Af[1], b0, b1);
      }
    }
  }

  float* Pb = g_part + (size_t)kc * NSEQ * DIMD + (size_t)m0 * DIMD;
#pragma unroll
  for (int mt = 0; mt < 2; mt++) {
#pragma unroll
    for (int nt = 0; nt < 8; nt++) {
      const int row0 = wm + mt * 16 + qr;
      const int col = wn + nt * 8 + 2 * qc;
      const float* o = O[mt][nt];
      *reinterpret_cast<float2*>(Pb + (size_t)row0 * DIMD + col) = make_float2(o[0], o[1]);
      *reinterpret_cast<float2*>(Pb + (size_t)(row0 + 8) * DIMD + col) = make_float2(o[2], o[3]);
    }
  }
}

__global__ void __launch_bounds__(256) reduce_kernel(float* __restrict__ out) {
  int i = blockIdx.x * 256 + threadIdx.x;
  const float4* p = reinterpret_cast<const float4*>(g_part);
  float4 a = p[i];
#pragma unroll
  for (int kc = 1; kc < KSPLIT; kc++) {
    float4 b = p[(size_t)kc * (NSEQ * DIMD / 4) + i];
    a.x += b.x; a.y += b.y; a.z += b.z; a.w += b.w;
  }
  reinterpret_cast<float4*>(out)[i] = a;
}

// =====================================================================
extern "C" void kernel_launch(void* const* d_in, const int* in_sizes, int n_in,
                              void* d_out, int out_size) {
  int mi = -1;
  for (int i = 0; i < n_in; i++)
    if (in_sizes[i] == NSEQ * NSEQ) { mi = i; break; }
  if (mi < 0) mi = 3;

  const void* p[7];
  int np = 0;
  for (int i = 0; i < n_in && np < 7; i++) {
    if (i == mi) continue;
    p[np++] = d_in[i];
  }
  const float* q = (const float*)p[0];
  const float* k = (const float*)p[1];
  const float* v = (const float*)p[2];
  const float* Qw = (const float*)p[3];
  const float* Kw = (const float*)p[4];
  const float* Vw = (const float*)p[5];
  const float* last = (const float*)p[6];
  const int* mask = (const int*)d_in[mi];
  float* out = (float*)d_out;

  const int GEMM_SMEM = 2 * 128 * PST * 4;

  cudaFuncSetAttribute(proj_tc_kernel, cudaFuncAttributeMaxDynamicSharedMemorySize, GEMM_SMEM);
  cudaFuncSetAttribute(out_tc_kernel, cudaFuncAttributeMaxDynamicSharedMemorySize, GEMM_SMEM);
  cudaFuncSetAttribute(attn_mma_kernel, cudaFuncAttributeMaxDynamicSharedMemorySize,
                       ATTN_SMEM_BYTES);

  maskbits_kernel<<<NSEQ * (NSEQ / 32) / 8, 256>>>(mask);
  proj_tc_kernel<<<dim3(NSEQ / 128, HEADS, 3), 256, GEMM_SMEM>>>(q, k, v, Qw, Kw, Vw);
  attn_mma_kernel<<<dim3(NSEQ / 128, HEADS), 512, ATTN_SMEM_BYTES>>>();
  out_tc_kernel<<<dim3(NSEQ / 128, KSPLIT), 256, GEMM_SMEM>>>(last);
  reduce_kernel<<<NSEQ * DIMD / 4 / 256, 256>>>(out);
}

// round 8
// speedup vs baseline: 7.5706x; 1.2363x over previous
#include <cuda_runtime.h>
#include <cstdint>

#define HEADS 16
#define DIMD 128
#define NSEQ 2048
/* exp(x*INV_SQRT_N) == exp2(x*C2) */
#define C2 0.0318793576f
#define KSPLIT 8

// ---------------- scratch (static device globals; no allocations) ----------------
__device__ __align__(16) uint32_t g_qp2[HEADS * NSEQ * 64];  // f16x2 packed
__device__ __align__(16) uint32_t g_kp2[HEADS * NSEQ * 64];  // f16x2 packed
__device__ __align__(16) uint32_t g_vp2[HEADS * NSEQ * 64];  // f16x2 packed
__device__ __align__(16) float g_ctx[NSEQ * HEADS * DIMD];
__device__ __align__(16) float g_part[KSPLIT * NSEQ * DIMD];
__device__ __align__(16) unsigned g_mbits[(NSEQ / 32) * NSEQ];  // [word][row]

// ---------------- helpers ----------------
__device__ __forceinline__ uint32_t f2tf(float x) {
  uint32_t r;
  asm("cvt.rna.tf32.f32 %0, %1;" : "=r"(r) : "f"(x));
  return r;
}
__device__ __forceinline__ uint32_t f2h2(float lo, float hi) {
  uint32_t r;
  asm("cvt.rn.f16x2.f32 %0, %1, %2;" : "=r"(r) : "f"(hi), "f"(lo));
  return r;
}
__device__ __forceinline__ uint32_t smem_u32(const void* p) {
  uint32_t a;
  asm("{ .reg .u64 t; cvta.to.shared.u64 t, %1; cvt.u32.u64 %0, t; }" : "=r"(a) : "l"(p));
  return a;
}

__device__ __forceinline__ void mma_tf32(float c[4], const uint32_t a[4],
                                         uint32_t b0, uint32_t b1) {
  asm volatile(
      "mma.sync.aligned.m16n8k8.row.col.f32.tf32.tf32.f32 "
      "{%0,%1,%2,%3}, {%4,%5,%6,%7}, {%8,%9}, {%0,%1,%2,%3};"
      : "+f"(c[0]), "+f"(c[1]), "+f"(c[2]), "+f"(c[3])
      : "r"(a[0]), "r"(a[1]), "r"(a[2]), "r"(a[3]), "r"(b0), "r"(b1));
}

__device__ __forceinline__ void mma_f16(float c[4], const uint32_t a[4],
                                        uint32_t b0, uint32_t b1) {
  asm volatile(
      "mma.sync.aligned.m16n8k16.row.col.f32.f16.f16.f32 "
      "{%0,%1,%2,%3}, {%4,%5,%6,%7}, {%8,%9}, {%0,%1,%2,%3};"
      : "+f"(c[0]), "+f"(c[1]), "+f"(c[2]), "+f"(c[3])
      : "r"(a[0]), "r"(a[1]), "r"(a[2]), "r"(a[3]), "r"(b0), "r"(b1));
}

__device__ __forceinline__ void ldmatrix_x4_trans(uint32_t& r0, uint32_t& r1,
                                                  uint32_t& r2, uint32_t& r3,
                                                  uint32_t addr) {
  asm volatile(
      "ldmatrix.sync.aligned.m8n8.x4.trans.shared.b16 {%0,%1,%2,%3}, [%4];"
      : "=r"(r0), "=r"(r1), "=r"(r2), "=r"(r3)
      : "r"(addr));
}

// ======================= kernel 0: pack mask into bits (transposed) ==========
__global__ void __launch_bounds__(256) maskbits_kernel(const int* __restrict__ mask) {
  int w = blockIdx.x * 8 + (threadIdx.x >> 5);  // global word id = i*64 + wj
  int lane = threadIdx.x & 31;
  int m = mask[(size_t)w * 32 + lane];
  unsigned bits = __ballot_sync(0xffffffffu, m != 0);
  if (lane == 0) g_mbits[(size_t)(w & 63) * NSEQ + (w >> 6)] = bits;
}

// ======================= kernel 1: projections (tf32, k-chunked, 2/SM) =======
// smem per chunk: Xs [128 rows][64 k] + Ws [128 e][64 k], stride 68 u32.
#define GST 68
__global__ void __launch_bounds__(256) proj_tc_kernel(
    const float* __restrict__ q, const float* __restrict__ k,
    const float* __restrict__ v, const float* __restrict__ Qw,
    const float* __restrict__ Kw, const float* __restrict__ Vw) {
  extern __shared__ float sm[];
  uint32_t* Xs = reinterpret_cast<uint32_t*>(sm);
  uint32_t* Ws = reinterpret_cast<uint32_t*>(sm) + 128 * GST;

  const int which = blockIdx.z;
  const float* A = (which == 0) ? q : (which == 1) ? k : v;
  const float* W = (which == 0) ? Qw : (which == 1) ? Kw : Vw;
  const int h = blockIdx.y;
  const int n0 = blockIdx.x * 128;
  const int tid = threadIdx.x;
  const int wid = tid >> 5;
  const int lane = tid & 31;
  const int qr = lane >> 2, qc = lane & 3;
  const int wm = (wid & 3) * 32;
  const int wn = (wid >> 2) * 64;

  float O[2][8][4];
#pragma unroll
  for (int mt = 0; mt < 2; mt++)
#pragma unroll
    for (int nt = 0; nt < 8; nt++)
#pragma unroll
      for (int e = 0; e < 4; e++) O[mt][nt][e] = 0.f;

  const float* Wh = W + (size_t)h * DIMD * DIMD;

  for (int kc = 0; kc < 2; kc++) {
    const int kb = kc * 64;
    __syncthreads();
    // X chunk: [128 rows][64 k]
    for (int idx = tid; idx < 128 * 16; idx += 256) {
      int r = idx >> 4, c4 = (idx & 15) << 2;
      float4 t = *reinterpret_cast<const float4*>(A + (size_t)(n0 + r) * DIMD + kb + c4);
      uint4 u = make_uint4(f2tf(t.x), f2tf(t.y), f2tf(t.z), f2tf(t.w));
      *reinterpret_cast<uint4*>(Xs + r * GST + c4) = u;
    }
    // W^T chunk: [128 e][64 k]
    for (int idx = tid; idx < 128 * 16; idx += 256) {
      int e = idx & 127, d4 = (idx >> 7) << 2;
      uint4 u = make_uint4(f2tf(Wh[(size_t)(kb + d4 + 0) * DIMD + e]),
                           f2tf(Wh[(size_t)(kb + d4 + 1) * DIMD + e]),
                           f2tf(Wh[(size_t)(kb + d4 + 2) * DIMD + e]),
                           f2tf(Wh[(size_t)(kb + d4 + 3) * DIMD + e]));
      *reinterpret_cast<uint4*>(Ws + e * GST + d4) = u;
    }
    __syncthreads();

#pragma unroll
    for (int k0 = 0; k0 < 64; k0 += 8) {
      uint32_t Af[2][4];
#pragma unroll
      for (int mt = 0; mt < 2; mt++) {
        const uint32_t* ab = Xs + (wm + mt * 16 + qr) * GST + k0 + qc;
        Af[mt][0] = ab[0];
        Af[mt][1] = ab[8 * GST];
        Af[mt][2] = ab[4];
        Af[mt][3] = ab[8 * GST + 4];
      }
#pragma unroll
      for (int nt = 0; nt < 8; nt++) {
        const uint32_t* bb = Ws + (wn + nt * 8 + qr) * GST + k0 + qc;
        uint32_t b0 = bb[0], b1 = bb[4];
        mma_tf32(O[0][nt], Af[0], b0, b1);
        mma_tf32(O[1][nt], Af[1], b0, b1);
      }
    }
  }

  uint32_t* Cb2 = (which == 0 ? g_qp2 : which == 1 ? g_kp2 : g_vp2) +
                  ((size_t)h * NSEQ + n0) * 64;
#pragma unroll
  for (int mt = 0; mt < 2; mt++) {
#pragma unroll
    for (int nt = 0; nt < 8; nt++) {
      const int row0 = wm + mt * 16 + qr;
      const int cu = (wn + nt * 8) / 2 + qc;
      const float* o = O[mt][nt];
      Cb2[(size_t)row0 * 64 + cu] = f2h2(o[0], o[1]);
      Cb2[(size_t)(row0 + 8) * 64 + cu] = f2h2(o[2], o[3]);
    }
  }
}

// ======================= kernel 2: attention, all-f16 MMA =====================
#define ATW 68
#define AT_K 0
#define AT_Q 8704
#define AT_PP 17408
#define AT_V 26112
#define AT_L 34816
#define ATTN_SMEM_BYTES ((34816 + 512) * 4)

__global__ void __launch_bounds__(512) attn_mma_kernel() {
  extern __shared__ uint32_t smu[];
  uint32_t* Ks2 = smu + AT_K;
  uint32_t* Qs2 = smu + AT_Q;
  uint32_t* Ps2 = smu + AT_PP;
  uint32_t* Vs2 = smu + AT_V;
  float* l_sh = reinterpret_cast<float*>(smu + AT_L);

  const int tid = threadIdx.x;
  const int wid = tid >> 5;
  const int lane = tid & 31;
  const int qr = lane >> 2;
  const int qc = lane & 3;
  const int wm = (wid & 3) * 32;
  const int wn = (wid >> 2) * 32;

  const int h = blockIdx.y;
  const int i0 = blockIdx.x * 128;

  const uint32_t* kp2 = g_kp2 + (size_t)h * NSEQ * 64;
  const uint32_t* qp2 = g_qp2 + (size_t)h * NSEQ * 64;
  const uint32_t* vp2 = g_vp2 + (size_t)h * NSEQ * 64;

  // K tile (persistent)
#pragma unroll
  for (int p = 0; p < 4; p++) {
    int idx = tid + p * 512;
    int r = idx >> 4, c4 = (idx & 15) << 2;
    uint4 t = *reinterpret_cast<const uint4*>(kp2 + (size_t)(i0 + r) * 64 + c4);
    *reinterpret_cast<uint4*>(Ks2 + r * ATW + c4) = t;
  }

  // prefetch Q tile 0
  uint4 qpre[4];
#pragma unroll
  for (int p = 0; p < 4; p++) {
    int idx = tid + p * 512;
    int r = idx >> 4, c4 = (idx & 15) << 2;
    qpre[p] = *reinterpret_cast<const uint4*>(qp2 + (size_t)r * 64 + c4);
  }

  const int lg = lane >> 3;
  const int vrow0 = (lane & 7) + ((lg & 1) << 3);
  const int vn0 = (wn >> 1) + ((lg >> 1) << 2);
  const uint32_t vbase = smem_u32(Vs2);

  float O[2][4][4];
#pragma unroll
  for (int mt = 0; mt < 2; mt++)
#pragma unroll
    for (int nt = 0; nt < 4; nt++)
#pragma unroll
      for (int e = 0; e < 4; e++) O[mt][nt][e] = 0.f;
  float L[4] = {0.f, 0.f, 0.f, 0.f};

  const int row_rel[4] = {qr, qr + 8, qr + 16, qr + 24};

  for (int jt = 0; jt < NSEQ / 128; jt++) {
    const int j0 = jt * 128;
    __syncthreads();  // prev PV done reading Ps2/Vs2

#pragma unroll
    for (int p = 0; p < 4; p++) {
      int idx = tid + p * 512;
      int r = idx >> 4, c4 = (idx & 15) << 2;
      *reinterpret_cast<uint4*>(Qs2 + r * ATW + c4) = qpre[p];
      uint4 tv = *reinterpret_cast<const uint4*>(vp2 + (size_t)(j0 + r) * 64 + c4);
      *reinterpret_cast<uint4*>(Vs2 + r * ATW + c4) = tv;
    }
    if (jt < NSEQ / 128 - 1) {
      const int jn = j0 + 128;
#pragma unroll
      for (int p = 0; p < 4; p++) {
        int idx = tid + p * 512;
        int r = idx >> 4, c4 = (idx & 15) << 2;
        qpre[p] = *reinterpret_cast<const uint4*>(qp2 + (size_t)(jn + r) * 64 + c4);
      }
    }
    __syncthreads();

    // ---- S = K · Q^T
    float S[2][4][4];
#pragma unroll
    for (int mt = 0; mt < 2; mt++)
#pragma unroll
      for (int nt = 0; nt < 4; nt++)
#pragma unroll
        for (int e = 0; e < 4; e++) S[mt][nt][e] = 0.f;

#pragma unroll
    for (int ks = 0; ks < 8; ks++) {
      const int k8 = ks * 8;
      uint32_t A[2][4];
#pragma unroll
      for (int mt = 0; mt < 2; mt++) {
        const uint32_t* ab = Ks2 + (wm + mt * 16 + qr) * ATW + k8 + qc;
        A[mt][0] = ab[0];
        A[mt][1] = ab[8 * ATW];
        A[mt][2] = ab[4];
        A[mt][3] = ab[8 * ATW + 4];
      }
#pragma unroll
      for (int nt = 0; nt < 4; nt++) {
        const uint32_t* bb = Qs2 + (wn + nt * 8 + qr) * ATW + k8 + qc;
        uint32_t b0 = bb[0], b1 = bb[4];
        mma_f16(S[0][nt], A[0], b0, b1);
        mma_f16(S[1][nt], A[1], b0, b1);
      }
    }

    // ---- masked exp (transposed mask: coalesced)
    const unsigned* mb = g_mbits + (size_t)((j0 + wn) >> 5) * NSEQ + i0 + wm;
    unsigned mw[4];
#pragma unroll
    for (int r = 0; r < 4; r++) mw[r] = mb[row_rel[r]];

    float lacc[4] = {0.f, 0.f, 0.f, 0.f};
#pragma unroll
    for (int mt = 0; mt < 2; mt++) {
#pragma unroll
      for (int nt = 0; nt < 4; nt++) {
        const int b0 = nt * 8 + 2 * qc;
        const unsigned w0 = mw[mt * 2], w1 = mw[mt * 2 + 1];
        float* s = S[mt][nt];
        float p0 = ((w0 >> b0) & 1u) ? exp2f(s[0] * C2) : 0.f;
        float p1 = ((w0 >> (b0 + 1)) & 1u) ? exp2f(s[1] * C2) : 0.f;
        float p2 = ((w1 >> b0) & 1u) ? exp2f(s[2] * C2) : 0.f;
        float p3 = ((w1 >> (b0 + 1)) & 1u) ? exp2f(s[3] * C2) : 0.f;
        s[0] = p0; s[1] = p1; s[2] = p2; s[3] = p3;
        lacc[mt * 2] += p0 + p1;
        lacc[mt * 2 + 1] += p2 + p3;
      }
    }
#pragma unroll
    for (int r = 0; r < 4; r++) {
      float v = lacc[r];
      v += __shfl_xor_sync(0xffffffffu, v, 1);
      v += __shfl_xor_sync(0xffffffffu, v, 2);
      L[r] += v;
    }

    // ---- P -> smem as f16x2
#pragma unroll
    for (int mt = 0; mt < 2; mt++) {
#pragma unroll
      for (int nt = 0; nt < 4; nt++) {
        const int row0 = wm + mt * 16 + qr;
        const int cu = (wn >> 1) + nt * 4 + qc;
        const float* s = S[mt][nt];
        Ps2[row0 * ATW + cu] = f2h2(s[0], s[1]);
        Ps2[(row0 + 8) * ATW + cu] = f2h2(s[2], s[3]);
      }
    }
    __syncthreads();

    // ---- O += P · V
    uint32_t vaddr0 = vbase + (uint32_t)(vrow0 * ATW + vn0) * 4u;
    uint32_t vaddr1 = vaddr0 + 32u;
#pragma unroll
    for (int ks = 0; ks < 8; ks++) {
      const int k8 = ks * 8;
      uint32_t A[2][4];
#pragma unroll
      for (int mt = 0; mt < 2; mt++) {
        const uint32_t* ab = Ps2 + (wm + mt * 16 + qr) * ATW + k8 + qc;
        A[mt][0] = ab[0];
        A[mt][1] = ab[8 * ATW];
        A[mt][2] = ab[4];
        A[mt][3] = ab[8 * ATW + 4];
      }
      uint32_t b0, b1, b2, b3;
      ldmatrix_x4_trans(b0, b1, b2, b3, vaddr0);
      mma_f16(O[0][0], A[0], b0, b1);
      mma_f16(O[1][0], A[1], b0, b1);
      mma_f16(O[0][1], A[0], b2, b3);
      mma_f16(O[1][1], A[1], b2, b3);
      ldmatrix_x4_trans(b0, b1, b2, b3, vaddr1);
      mma_f16(O[0][2], A[0], b0, b1);
      mma_f16(O[1][2], A[1], b0, b1);
      mma_f16(O[0][3], A[0], b2, b3);
      mma_f16(O[1][3], A[1], b2, b3);
      vaddr0 += 16u * ATW * 4u;
      vaddr1 += 16u * ATW * 4u;
    }
  }

  if (qc == 0) {
#pragma unroll
    for (int r = 0; r < 4; r++)
      l_sh[(wid >> 2) * 128 + wm + row_rel[r]] = L[r];
  }
  __syncthreads();
  float linv[4];
#pragma unroll
  for (int r = 0; r < 4; r++) {
    int row = wm + row_rel[r];
    linv[r] = 1.f / (l_sh[row] + l_sh[128 + row] + l_sh[256 + row] + l_sh[384 + row]);
  }

#pragma unroll
  for (int mt = 0; mt < 2; mt++) {
#pragma unroll
    for (int nt = 0; nt < 4; nt++) {
      const int row0 = wm + mt * 16 + qr;
      const int col = h * DIMD + wn + nt * 8 + 2 * qc;
      const float* o = O[mt][nt];
      float2 a = make_float2(o[0] * linv[mt * 2], o[1] * linv[mt * 2]);
      float2 b = make_float2(o[2] * linv[mt * 2 + 1], o[3] * linv[mt * 2 + 1]);
      *reinterpret_cast<float2*>(g_ctx + (size_t)(i0 + row0) * (HEADS * DIMD) + col) = a;
      *reinterpret_cast<float2*>(g_ctx + (size_t)(i0 + row0 + 8) * (HEADS * DIMD) + col) = b;
    }
  }
}

// ======================= kernel 3: out (tf32, k-chunked, 2/SM, split-K) ======
__global__ void __launch_bounds__(256) out_tc_kernel(const float* __restrict__ last) {
  extern __shared__ float sm[];
  uint32_t* Xs = reinterpret_cast<uint32_t*>(sm);
  uint32_t* Bt = reinterpret_cast<uint32_t*>(sm) + 128 * GST;

  const int m0 = blockIdx.x * 128;
  const int kc = blockIdx.y;
  const int tid = threadIdx.x;
  const int wid = tid >> 5;
  const int lane = tid & 31;
  const int qr = lane >> 2, qc = lane & 3;
  const int wm = (wid & 3) * 32;
  const int wn = (wid >> 2) * 64;

  float O[2][8][4];
#pragma unroll
  for (int mt = 0; mt < 2; mt++)
#pragma unroll
    for (int nt = 0; nt < 8; nt++)
#pragma unroll
      for (int e = 0; e < 4; e++) O[mt][nt][e] = 0.f;

  for (int ks = 0; ks < 4; ks++) {
    const int kb = kc * 256 + ks * 64;
    __syncthreads();
    for (int idx = tid; idx < 128 * 16; idx += 256) {
      int r = idx >> 4, c4 = (idx & 15) << 2;
      float4 t = *reinterpret_cast<const float4*>(
          g_ctx + (size_t)(m0 + r) * (HEADS * DIMD) + kb + c4);
      uint4 u = make_uint4(f2tf(t.x), f2tf(t.y), f2tf(t.z), f2tf(t.w));
      *reinterpret_cast<uint4*>(Xs + r * GST + c4) = u;
    }
    for (int idx = tid; idx < 128 * 16; idx += 256) {
      int e = idx & 127, k4 = (idx >> 7) << 2;
      uint4 u = make_uint4(f2tf(last[(size_t)(kb + k4 + 0) * DIMD + e]),
                           f2tf(last[(size_t)(kb + k4 + 1) * DIMD + e]),
                           f2tf(last[(size_t)(kb + k4 + 2) * DIMD + e]),
                           f2tf(last[(size_t)(kb + k4 + 3) * DIMD + e]));
      *reinterpret_cast<uint4*>(Bt + e * GST + k4) = u;
    }
    __syncthreads();

#pragma unroll
    for (int k0 = 0; k0 < 64; k0 += 8) {
      uint32_t Af[2][4];
#pragma unroll
      for (int mt = 0; mt < 2; mt++) {
        const uint32_t* ab = Xs + (wm + mt * 16 + qr) * GST + k0 + qc;
        Af[mt][0] = ab[0];
        Af[mt][1] = ab[8 * GST];
        Af[mt][2] = ab[4];
        Af[mt][3] = ab[8 * GST + 4];
      }
#pragma unroll
      for (int nt = 0; nt < 8; nt++) {
        const uint32_t* bb = Bt + (wn + nt * 8 + qr) * GST + k0 + qc;
        uint32_t b0 = bb[0], b1 = bb[4];
        mma_tf32(O[0][nt], Af[0], b0, b1);
        mma_tf32(O[1][nt], Af[1], b0, b1);
      }
    }
  }

  float* Pb = g_part + (size_t)kc * NSEQ * DIMD + (size_t)m0 * DIMD;
#pragma unroll
  for (int mt = 0; mt < 2; mt++) {
#pragma unroll
    for (int nt = 0; nt < 8; nt++) {
      const int row0 = wm + mt * 16 + qr;
      const int col = wn + nt * 8 + 2 * qc;
      const float* o = O[mt][nt];
      *reinterpret_cast<float2*>(Pb + (size_t)row0 * DIMD + col) = make_float2(o[0], o[1]);
      *reinterpret_cast<float2*>(Pb + (size_t)(row0 + 8) * DIMD + col) = make_float2(o[2], o[3]);
    }
  }
}

__global__ void __launch_bounds__(256) reduce_kernel(float* __restrict__ out) {
  int i = blockIdx.x * 256 + threadIdx.x;
  const float4* p = reinterpret_cast<const float4*>(g_part);
  float4 a = p[i];
#pragma unroll
  for (int kc = 1; kc < KSPLIT; kc++) {
    float4 b = p[(size_t)kc * (NSEQ * DIMD / 4) + i];
    a.x += b.x; a.y += b.y; a.z += b.z; a.w += b.w;
  }
  reinterpret_cast<float4*>(out)[i] = a;
}

// =====================================================================
extern "C" void kernel_launch(void* const* d_in, const int* in_sizes, int n_in,
                              void* d_out, int out_size) {
  int mi = -1;
  for (int i = 0; i < n_in; i++)
    if (in_sizes[i] == NSEQ * NSEQ) { mi = i; break; }
  if (mi < 0) mi = 3;

  const void* p[7];
  int np = 0;
  for (int i = 0; i < n_in && np < 7; i++) {
    if (i == mi) continue;
    p[np++] = d_in[i];
  }
  const float* q = (const float*)p[0];
  const float* k = (const float*)p[1];
  const float* v = (const float*)p[2];
  const float* Qw = (const float*)p[3];
  const float* Kw = (const float*)p[4];
  const float* Vw = (const float*)p[5];
  const float* last = (const float*)p[6];
  const int* mask = (const int*)d_in[mi];
  float* out = (float*)d_out;

  const int GEMM_SMEM = 2 * 128 * GST * 4;  // 69,632 B -> 2 blocks/SM

  cudaFuncSetAttribute(proj_tc_kernel, cudaFuncAttributeMaxDynamicSharedMemorySize, GEMM_SMEM);
  cudaFuncSetAttribute(out_tc_kernel, cudaFuncAttributeMaxDynamicSharedMemorySize, GEMM_SMEM);
  cudaFuncSetAttribute(attn_mma_kernel, cudaFuncAttributeMaxDynamicSharedMemorySize,
                       ATTN_SMEM_BYTES);

  maskbits_kernel<<<NSEQ * (NSEQ / 32) / 8, 256>>>(mask);
  proj_tc_kernel<<<dim3(NSEQ / 128, HEADS, 3), 256, GEMM_SMEM>>>(q, k, v, Qw, Kw, Vw);
  attn_mma_kernel<<<dim3(NSEQ / 128, HEADS), 512, ATTN_SMEM_BYTES>>>();
  out_tc_kernel<<<dim3(NSEQ / 128, KSPLIT), 256, GEMM_SMEM>>>(last);
  reduce_kernel<<<NSEQ * DIMD / 4 / 256, 256>>>(out);
}